// round 13
// baseline (speedup 1.0000x reference)
#include <cuda_runtime.h>
#include <cuda_bf16.h>
#include <cstdint>

// Problem constants (fixed by setup_inputs)
#define T_TOK 2048
#define NEXP  8
#define HD    1024
#define ID    4096
#define NSLOT 4096
#define PADROWS (NSLOT + 256)
#define NTILES  72              // max m-tiles of 64 over experts

// permuted-k geometry: groups padded to 16, totals padded to 64
#define K13P   1152             // >= 1024 + 8*15, mult of 64
#define K2P    4608             // >= 4096 + 32*15, mult of 64
#define SCHED13 72              // 16-step entries
#define SCHED2  288

// ---------------- scratch (static device globals; no allocation) -----------
__device__ int   g_counts[NEXP];
__device__ int   g_base[NEXP];
__device__ int   g_slot_tok[NSLOT];
__device__ int   g_slot_e[NSLOT];
__device__ float g_slot_w[NSLOT];
__device__ int   g_token_slot[NSLOT];
__device__ int   g_tile_e[NTILES];
__device__ int   g_tile_m0[NTILES];

__device__ int   g_perm13[NEXP * K13P];
__device__ int   g_perm2 [NEXP * K2P];
__device__ int   g_sched13[NEXP * SCHED13];   // gid | 0x100 flush flag
__device__ int   g_sched2 [NEXP * SCHED2];
__device__ int   g_nch13[NEXP];
__device__ int   g_nch2 [NEXP];

// exact-integer weights (bf16 of q-8), k-permuted, [e][n][k']
__device__ __align__(256) __nv_bfloat16 g_q13p[(size_t)NEXP * 2 * ID * K13P];
__device__ __align__(256) __nv_bfloat16 g_q2p [(size_t)NEXP * HD * K2P];
// hi/lo split activations, k-permuted per slot's expert
__device__ __align__(256) __nv_bfloat16 g_xah [(size_t)PADROWS * K13P];
__device__ __align__(256) __nv_bfloat16 g_xal [(size_t)PADROWS * K13P];
__device__ __align__(256) __nv_bfloat16 g_acth[(size_t)PADROWS * K2P];
__device__ __align__(256) __nv_bfloat16 g_actl[(size_t)PADROWS * K2P];
// zero row for padded B gathers (device globals are zero-initialized)
__device__ __align__(256) __nv_bfloat16 g_zrow[K13P];

__device__ __align__(256) float g_outslot[(size_t)NSLOT * HD];  // gemm2 out fp32

// ---------------- helpers ---------------------------------------------------
__device__ __forceinline__ uint32_t smem_u32(const void* p) {
    uint32_t a;
    asm("{ .reg .u64 t; cvta.to.shared.u64 t, %1; cvt.u32.u64 %0, t; }"
        : "=r"(a) : "l"(p));
    return a;
}
__device__ __forceinline__ void ldsm4(uint32_t* r, uint32_t a) {
    asm volatile("ldmatrix.sync.aligned.m8n8.x4.shared.b16 {%0,%1,%2,%3}, [%4];"
                 : "=r"(r[0]), "=r"(r[1]), "=r"(r[2]), "=r"(r[3]) : "r"(a));
}
__device__ __forceinline__ void cpasync16(uint32_t saddr, const void* gaddr) {
    asm volatile("cp.async.cg.shared.global [%0], [%1], 16;"
                 :: "r"(saddr), "l"(gaddr) : "memory");
}
#define CP_COMMIT() asm volatile("cp.async.commit_group;" ::: "memory")
#define CP_WAIT0()  asm volatile("cp.async.wait_group 0;" ::: "memory")

__device__ __forceinline__ void mma16816(float* d, const uint32_t* a,
                                         uint32_t b0, uint32_t b1) {
    asm volatile(
        "mma.sync.aligned.m16n8k16.row.col.f32.bf16.bf16.f32 "
        "{%0,%1,%2,%3}, {%4,%5,%6,%7}, {%8,%9}, {%0,%1,%2,%3};"
        : "+f"(d[0]), "+f"(d[1]), "+f"(d[2]), "+f"(d[3])
        : "r"(a[0]), "r"(a[1]), "r"(a[2]), "r"(a[3]), "r"(b0), "r"(b1));
}
__device__ __forceinline__ void split2(float v, __nv_bfloat16& h, __nv_bfloat16& l) {
    h = __float2bfloat16(v);
    l = __float2bfloat16(v - __bfloat162float(h));
}

// ---------------- routing + permutation build (grid = 17 blocks) -----------
__global__ void k_route(const float* __restrict__ logits,
                        const int* __restrict__ gi13,
                        const int* __restrict__ gi2) {
    const int tid = threadIdx.x;
    if (blockIdx.x == 0) {
        __shared__ int   csh[NEXP];
        __shared__ int   cur[NEXP];
        __shared__ int   te[NSLOT];
        __shared__ float tw[NSLOT];
        if (tid < NEXP) csh[tid] = 0;
        __syncthreads();
        for (int t = tid; t < T_TOK; t += 256) {
            float l[NEXP];
#pragma unroll
            for (int e = 0; e < NEXP; e++) l[e] = logits[t * NEXP + e];
            int i1 = 0; float m1 = l[0];
            int i2 = -1; float m2 = -3.0e38f;
#pragma unroll
            for (int e = 1; e < NEXP; e++) {
                if (l[e] > m1) { m2 = m1; i2 = i1; m1 = l[e]; i1 = e; }
                else if (l[e] > m2) { m2 = l[e]; i2 = e; }
            }
            float r  = expf(m2 - m1);
            float w1 = 1.0f / (1.0f + r);
            float w2 = r * w1;
            te[t * 2 + 0] = i1;  te[t * 2 + 1] = i2;
            tw[t * 2 + 0] = w1;  tw[t * 2 + 1] = w2;
            atomicAdd(&csh[i1], 1);
            atomicAdd(&csh[i2], 1);
        }
        __syncthreads();
        if (tid == 0) {
            int acc = 0;
            for (int e = 0; e < NEXP; e++) {
                g_counts[e] = csh[e];
                g_base[e]   = acc;
                cur[e]      = acc;
                acc += csh[e];
            }
            int nt = 0;
            for (int e = 0; e < NEXP; e++)
                for (int m0 = 0; m0 < csh[e]; m0 += 64) {
                    g_tile_e[nt]  = e;
                    g_tile_m0[nt] = m0;
                    nt++;
                }
            for (; nt < NTILES; nt++) g_tile_e[nt] = -1;
        }
        __syncthreads();
        for (int t = tid; t < T_TOK; t += 256) {
#pragma unroll
            for (int j = 0; j < 2; j++) {
                int e   = te[t * 2 + j];
                int pos = atomicAdd(&cur[e], 1);
                g_slot_tok[pos]         = t;
                g_slot_e[pos]           = e;
                g_slot_w[pos]           = tw[t * 2 + j];
                g_token_slot[t * 2 + j] = pos;
            }
        }
    } else {
        // permutation builder
        const int pb  = blockIdx.x - 1;     // 0..15
        const int mat = pb >> 3;            // 0: w13, 1: w2
        const int e   = pb & 7;
        const int K   = mat ? ID : HD;
        const int G   = mat ? 32 : 8;
        const int KP  = mat ? K2P : K13P;
        const int SC  = mat ? SCHED2 : SCHED13;
        const int* gi = mat ? (gi2 + e * ID) : (gi13 + e * HD);
        int* perm  = mat ? (g_perm2 + e * K2P)   : (g_perm13 + e * K13P);
        int* sched = mat ? (g_sched2 + e * SCHED2) : (g_sched13 + e * SCHED13);

        __shared__ int lh[256 * 32];        // per-thread local hist
        __shared__ int gstart[33];
        const int perth = K / 256;          // 4 or 16
        const int kb = tid * perth;
        for (int g = 0; g < G; g++) lh[tid * G + g] = 0;
        __syncthreads();
        for (int i = 0; i < perth; i++) lh[tid * G + gi[kb + i]]++;
        __syncthreads();
        if (tid == 0) {
            int acc = 0, step = 0;
            for (int g = 0; g < G; g++) {
                int c = 0;
                for (int t = 0; t < 256; t++) c += lh[t * G + g];
                gstart[g] = acc;
                int stp = (c + 15) >> 4;
                for (int s = 0; s < stp; s++)
                    sched[step++] = g | ((s == stp - 1) ? 0x100 : 0);
                acc += stp << 4;
            }
            int nch = (step + 3) >> 2;
            if (mat) g_nch2[e] = nch; else g_nch13[e] = nch;
            for (; step < nch * 4; step++) sched[step] = 0;
            for (; step < SC; step++) sched[step] = 0;
        }
        __syncthreads();
        if (tid < G) {
            int off = gstart[tid];
            for (int t = 0; t < 256; t++) {
                int c = lh[t * G + tid];
                lh[t * G + tid] = off;
                off += c;
            }
        }
        __syncthreads();
        for (int i = tid; i < KP; i += 256) perm[i] = -1;
        __syncthreads();
        for (int i = 0; i < perth; i++) {
            int k = kb + i;
            int g = gi[k];
            perm[lh[tid * G + g]++] = k;
        }
    }
}

// ---------------- prolog: build exact-int bf16 weight matrices -------------
// w13: CTA = (n-tile of 64, e); smem-staged nibble gather along permuted k.
// Output keeps ORIGINAL column order; gemm1 handles n-permutation at gather.
__global__ void k_split_w13(const int* __restrict__ qw) {
    __shared__ int sq[128 * 65];            // [kp][nn], padded stride
    __shared__ int sperm[K13P];
    const int e  = blockIdx.y;
    const int n0 = blockIdx.x * 64;
    const int tid = threadIdx.x;
    for (int i = tid; i < 128 * 64; i += 256) {
        int kp = i >> 6, nn = i & 63;
        sq[kp * 65 + nn] = qw[((size_t)e * 128 + kp) * 8192 + n0 + nn];
    }
    for (int i = tid; i < K13P; i += 256) sperm[i] = g_perm13[e * K13P + i];
    __syncthreads();
    for (int c = tid; c < 64 * (K13P / 8); c += 256) {
        int oct = c % (K13P / 8);
        int nn  = c / (K13P / 8);
        alignas(16) __nv_bfloat16 out[8];
        int4 p0 = *(const int4*)&sperm[oct * 8];
        int4 p1 = *(const int4*)&sperm[oct * 8 + 4];
        int pk[8] = {p0.x, p0.y, p0.z, p0.w, p1.x, p1.y, p1.z, p1.w};
#pragma unroll
        for (int j = 0; j < 8; j++) {
            int k = pk[j];
            int v = (k < 0) ? 0 : (((sq[(k >> 3) * 65 + nn] >> ((k & 7) * 4)) & 15) - 8);
            out[j] = __float2bfloat16((float)v);
        }
        *(uint4*)(g_q13p + ((size_t)e * 8192 + n0 + nn) * K13P + oct * 8) = *(uint4*)out;
    }
}

// w2: CTA = (n-tile of 8, e)
__global__ void k_split_w2(const int* __restrict__ qw) {
    __shared__ int sq[512 * 9];             // [kp][nn], padded
    __shared__ int sperm[K2P];
    const int e  = blockIdx.y;
    const int n0 = blockIdx.x * 8;
    const int tid = threadIdx.x;
    for (int i = tid; i < 512 * 8; i += 256) {
        int kp = i >> 3, nn = i & 7;
        sq[kp * 9 + nn] = qw[((size_t)e * 512 + kp) * 1024 + n0 + nn];
    }
    for (int i = tid; i < K2P; i += 256) sperm[i] = g_perm2[e * K2P + i];
    __syncthreads();
    for (int c = tid; c < 8 * (K2P / 8); c += 256) {
        int oct = c % (K2P / 8);
        int nn  = c / (K2P / 8);
        alignas(16) __nv_bfloat16 out[8];
        int4 p0 = *(const int4*)&sperm[oct * 8];
        int4 p1 = *(const int4*)&sperm[oct * 8 + 4];
        int pk[8] = {p0.x, p0.y, p0.z, p0.w, p1.x, p1.y, p1.z, p1.w};
#pragma unroll
        for (int j = 0; j < 8; j++) {
            int k = pk[j];
            int v = (k < 0) ? 0 : (((sq[(k >> 3) * 9 + nn] >> ((k & 7) * 4)) & 15) - 8);
            out[j] = __float2bfloat16((float)v);
        }
        *(uint4*)(g_q2p + ((size_t)e * 1024 + n0 + nn) * K2P + oct * 8) = *(uint4*)out;
    }
}

// ---------------- prolog: gather x (permuted k), split hi/lo ----------------
__global__ void k_split_x(const float* __restrict__ x) {
    int id  = blockIdx.x * 256 + threadIdx.x;
    int oct = id % (K13P / 8);
    int s   = id / (K13P / 8);
    int e   = g_slot_e[s];
    int tok = g_slot_tok[s];
    const int* pm = g_perm13 + e * K13P + oct * 8;
    alignas(16) __nv_bfloat16 h[8], l[8];
#pragma unroll
    for (int j = 0; j < 8; j++) {
        int k = pm[j];
        float v = (k < 0) ? 0.0f : x[(size_t)tok * HD + k];
        split2(v, h[j], l[j]);
    }
    size_t o = (size_t)s * K13P + oct * 8;
    *(uint4*)(g_xah + o) = *(uint4*)h;
    *(uint4*)(g_xal + o) = *(uint4*)l;
}

// ---------------- GEMM geometry --------------------------------------------
#define PITCH_B 144
#define AMAT    (64 * PITCH_B)               // 9216
#define BMAT    (128 * PITCH_B)              // 18432
#define STAGE_BYTES (2 * AMAT + BMAT)        // 36864
#define GTHREADS    256

// ---------------- GEMM1: fused act epilogue --------------------------------
// Block 64 x 128 where the 128 columns are (gate,up)-interleaved at permuted
// intermediate index j: col c -> original n = perm2[jt + c/2] + (c&1)*ID.
// 2-term exact-int MMA with per-column group-scale flush; epilogue computes
// silu(gate)*up in registers and writes hi/lo bf16 direct to g_acth/g_actl.
__global__ __launch_bounds__(GTHREADS, 2) void k_gemm1(const float* __restrict__ sc) {
    extern __shared__ __align__(128) char smem[];
    const int e = g_tile_e[blockIdx.x];
    if (e < 0) return;
    const int m0   = g_tile_m0[blockIdx.x];
    const int cnt  = g_counts[e];
    const int base = g_base[e];
    const int jt   = blockIdx.y * 64;       // permuted-j tile base
    const int tid  = threadIdx.x;
    const int lid  = tid & 31;
    const int wid  = tid >> 5;
    const int wm   = (wid >> 2) * 32;
    const int wn   = (wid & 3) * 32;

    const __nv_bfloat16* Axh = g_xah + (size_t)(base + m0) * K13P;
    const __nv_bfloat16* Axl = g_xal + (size_t)(base + m0) * K13P;
    const int nch = g_nch13[e];

    const uint32_t sbase = smem_u32(smem);
    float* stile = (float*)(smem + 2 * STAGE_BYTES);                     // [8][128]
    const __nv_bfloat16** rowp =
        (const __nv_bfloat16**)(smem + 2 * STAGE_BYTES + 8 * 128 * 4);   // [128]
    int* ssched = (int*)(smem + 2 * STAGE_BYTES + 8 * 128 * 4 + 128 * 8);

    // per-row B source pointers (n-permutation + gate/up interleave)
    if (tid < 128) {
        int p = g_perm2[e * K2P + jt + (tid >> 1)];
        rowp[tid] = (p < 0) ? g_zrow
                  : g_q13p + ((size_t)e * 8192 + p + (tid & 1) * ID) * K13P;
    }
    // per-column k-group scales, gathered at permuted positions
    for (int i = tid; i < 8 * 128; i += GTHREADS) {
        int g = i >> 7, c = i & 127;
        int p = g_perm2[e * K2P + jt + (c >> 1)];
        int nsrc = (p < 0) ? 0 : p + (c & 1) * ID;
        stile[i] = sc[((size_t)e * 8 + g) * 8192 + nsrc];
    }
    for (int i = tid; i < nch * 4; i += GTHREADS) ssched[i] = g_sched13[e * SCHED13 + i];
    __syncthreads();    // rowp must be visible before first fill

    float acc[2][4][4], pacc[2][4][4];
#pragma unroll
    for (int i = 0; i < 2; i++)
#pragma unroll
        for (int j = 0; j < 4; j++)
#pragma unroll
            for (int k = 0; k < 4; k++) { acc[i][j][k] = 0.0f; pacc[i][j][k] = 0.0f; }

    const uint32_t a_row  = (uint32_t)(lid & 15);
    const uint32_t a_koff = (uint32_t)((lid >> 4) * 16);
    const uint32_t b_row  = (uint32_t)(((lid >> 4) & 1) * 8 + (lid & 7));
    const uint32_t b_koff = (uint32_t)(((lid >> 3) & 1) * 16);
    const int lc = (lid & 3) * 2;

    auto issue_stage = [&](uint32_t sb, int k0) {
#pragma unroll
        for (int it = 0; it < 8; it++) {
            int j = it * GTHREADS + tid;
            const __nv_bfloat16* src;
            uint32_t dst;
            if (j < 1024) {
                int mat = j >> 9, jj = j & 511;
                int r = jj >> 3, c = jj & 7;
                src = (mat ? Axl : Axh) + (size_t)r * K13P + k0 + c * 8;
                dst = (uint32_t)(mat * AMAT + r * PITCH_B + c * 16);
            } else {
                int jb = j - 1024;
                int r = jb >> 3, c = jb & 7;
                src = rowp[r] + k0 + c * 8;
                dst = (uint32_t)(2 * AMAT + r * PITCH_B + c * 16);
            }
            cpasync16(sb + dst, src);
        }
        CP_COMMIT();
    };

    issue_stage(sbase, 0);

    for (int ch = 0; ch < nch; ch++) {
        CP_WAIT0();
        __syncthreads();
        const uint32_t buf = sbase + (uint32_t)((ch & 1) * STAGE_BYTES);
        if (ch + 1 < nch)
            issue_stage(sbase + (uint32_t)(((ch + 1) & 1) * STAGE_BYTES),
                        (ch + 1) * 64);
#pragma unroll
        for (int s = 0; s < 4; s++) {
            uint32_t ah[2][4], al[2][4];
#pragma unroll
            for (int mi = 0; mi < 2; mi++) {
                uint32_t ra = buf + (uint32_t)((wm + mi * 16 + a_row) * PITCH_B)
                                  + (uint32_t)(s * 32) + a_koff;
                ldsm4(ah[mi], ra);
                ldsm4(al[mi], ra + AMAT);
            }
            uint32_t bq[2][4];
#pragma unroll
            for (int p = 0; p < 2; p++) {
                uint32_t rb = buf + 2u * AMAT
                                  + (uint32_t)((wn + p * 16 + b_row) * PITCH_B)
                                  + (uint32_t)(s * 32) + b_koff;
                ldsm4(bq[p], rb);
            }
#pragma unroll
            for (int ni = 0; ni < 4; ni++) {
                uint32_t b0 = bq[ni >> 1][(ni & 1) * 2];
                uint32_t b1 = bq[ni >> 1][(ni & 1) * 2 + 1];
#pragma unroll
                for (int mi = 0; mi < 2; mi++) {
                    mma16816(pacc[mi][ni], ah[mi], b0, b1);
                    mma16816(pacc[mi][ni], al[mi], b0, b1);
                }
            }
            int ent = ssched[ch * 4 + s];
            if (ent & 0x100) {
                const float* srow = stile + (ent & 0xFF) * 128;
#pragma unroll
                for (int ni = 0; ni < 4; ni++) {
                    float s0 = srow[wn + ni * 8 + lc];
                    float s1 = srow[wn + ni * 8 + lc + 1];
#pragma unroll
                    for (int mi = 0; mi < 2; mi++) {
                        acc[mi][ni][0] += s0 * pacc[mi][ni][0];
                        acc[mi][ni][1] += s1 * pacc[mi][ni][1];
                        acc[mi][ni][2] += s0 * pacc[mi][ni][2];
                        acc[mi][ni][3] += s1 * pacc[mi][ni][3];
                        pacc[mi][ni][0] = 0.0f; pacc[mi][ni][1] = 0.0f;
                        pacc[mi][ni][2] = 0.0f; pacc[mi][ni][3] = 0.0f;
                    }
                }
            }
        }
    }

    // fused epilogue: cols (lc, lc+1) = (gate_j, up_j); silu + split -> act
    const int lr = lid >> 2;
#pragma unroll
    for (int mi = 0; mi < 2; mi++) {
#pragma unroll
        for (int half = 0; half < 2; half++) {
            int row = m0 + wm + mi * 16 + half * 8 + lr;
            if (row < cnt) {
                int gs = base + row;
#pragma unroll
                for (int ni = 0; ni < 4; ni++) {
                    float g = acc[mi][ni][half * 2];
                    float u = acc[mi][ni][half * 2 + 1];
                    float a = g / (1.0f + expf(-g)) * u;
                    __nv_bfloat16 h, l;
                    split2(a, h, l);
                    int jp = jt + ((wn + ni * 8 + lc) >> 1);
                    g_acth[(size_t)gs * K2P + jp] = h;
                    g_actl[(size_t)gs * K2P + jp] = l;
                }
            }
        }
    }
}

#define SMEM1 (2 * STAGE_BYTES + 8 * 128 * 4 + 128 * 8 + SCHED13 * 4 + 224)

// ---------------- GEMM2: act @ q2^T with group-scale flush -----------------
__global__ __launch_bounds__(GTHREADS, 2) void k_gemm2(const float* __restrict__ sc) {
    extern __shared__ __align__(128) char smem[];
    const int e = g_tile_e[blockIdx.x];
    if (e < 0) return;
    const int m0   = g_tile_m0[blockIdx.x];
    const int cnt  = g_counts[e];
    const int base = g_base[e];
    const int n0   = blockIdx.y * 128;
    const int tid  = threadIdx.x;
    const int lid  = tid & 31;
    const int wid  = tid >> 5;
    const int wm   = (wid >> 2) * 32;
    const int wn   = (wid & 3) * 32;

    const __nv_bfloat16* Axh = g_acth + (size_t)(base + m0) * K2P;
    const __nv_bfloat16* Axl = g_actl + (size_t)(base + m0) * K2P;
    const __nv_bfloat16* Bq  = g_q2p + (size_t)e * HD * K2P + (size_t)n0 * K2P;
    const int nch = g_nch2[e];

    const uint32_t sbase = smem_u32(smem);
    float* stile = (float*)(smem + 2 * STAGE_BYTES);             // [32][128]
    int*   ssched = (int*)(smem + 2 * STAGE_BYTES + 32 * 128 * 4);

    for (int i = tid; i < 32 * 128; i += GTHREADS) {
        int g = i >> 7, j = i & 127;
        stile[i] = sc[((size_t)e * 32 + g) * 1024 + n0 + j];
    }
    for (int i = tid; i < nch * 4; i += GTHREADS) ssched[i] = g_sched2[e * SCHED2 + i];

    float acc[2][4][4], pacc[2][4][4];
#pragma unroll
    for (int i = 0; i < 2; i++)
#pragma unroll
        for (int j = 0; j < 4; j++)
#pragma unroll
            for (int k = 0; k < 4; k++) { acc[i][j][k] = 0.0f; pacc[i][j][k] = 0.0f; }

    const uint32_t a_row  = (uint32_t)(lid & 15);
    const uint32_t a_koff = (uint32_t)((lid >> 4) * 16);
    const uint32_t b_row  = (uint32_t)(((lid >> 4) & 1) * 8 + (lid & 7));
    const uint32_t b_koff = (uint32_t)(((lid >> 3) & 1) * 16);
    const int lc = (lid & 3) * 2;

    auto issue_stage = [&](uint32_t sb, int k0) {
#pragma unroll
        for (int it = 0; it < 8; it++) {
            int j = it * GTHREADS + tid;
            const __nv_bfloat16* src;
            uint32_t dst;
            if (j < 1024) {
                int mat = j >> 9, jj = j & 511;
                int r = jj >> 3, c = jj & 7;
                src = (mat ? Axl : Axh) + (size_t)r * K2P + k0 + c * 8;
                dst = (uint32_t)(mat * AMAT + r * PITCH_B + c * 16);
            } else {
                int jb = j - 1024;
                int r = jb >> 3, c = jb & 7;
                src = Bq + (size_t)r * K2P + k0 + c * 8;
                dst = (uint32_t)(2 * AMAT + r * PITCH_B + c * 16);
            }
            cpasync16(sb + dst, src);
        }
        CP_COMMIT();
    };

    issue_stage(sbase, 0);

    for (int ch = 0; ch < nch; ch++) {
        CP_WAIT0();
        __syncthreads();
        const uint32_t buf = sbase + (uint32_t)((ch & 1) * STAGE_BYTES);
        if (ch + 1 < nch)
            issue_stage(sbase + (uint32_t)(((ch + 1) & 1) * STAGE_BYTES),
                        (ch + 1) * 64);
#pragma unroll
        for (int s = 0; s < 4; s++) {
            uint32_t ah[2][4], al[2][4];
#pragma unroll
            for (int mi = 0; mi < 2; mi++) {
                uint32_t ra = buf + (uint32_t)((wm + mi * 16 + a_row) * PITCH_B)
                                  + (uint32_t)(s * 32) + a_koff;
                ldsm4(ah[mi], ra);
                ldsm4(al[mi], ra + AMAT);
            }
            uint32_t bq[2][4];
#pragma unroll
            for (int p = 0; p < 2; p++) {
                uint32_t rb = buf + 2u * AMAT
                                  + (uint32_t)((wn + p * 16 + b_row) * PITCH_B)
                                  + (uint32_t)(s * 32) + b_koff;
                ldsm4(bq[p], rb);
            }
#pragma unroll
            for (int ni = 0; ni < 4; ni++) {
                uint32_t b0 = bq[ni >> 1][(ni & 1) * 2];
                uint32_t b1 = bq[ni >> 1][(ni & 1) * 2 + 1];
#pragma unroll
                for (int mi = 0; mi < 2; mi++) {
                    mma16816(pacc[mi][ni], ah[mi], b0, b1);
                    mma16816(pacc[mi][ni], al[mi], b0, b1);
                }
            }
            int ent = ssched[ch * 4 + s];
            if (ent & 0x100) {
                const float* srow = stile + (ent & 0xFF) * 128;
#pragma unroll
                for (int ni = 0; ni < 4; ni++) {
                    float s0 = srow[wn + ni * 8 + lc];
                    float s1 = srow[wn + ni * 8 + lc + 1];
#pragma unroll
                    for (int mi = 0; mi < 2; mi++) {
                        acc[mi][ni][0] += s0 * pacc[mi][ni][0];
                        acc[mi][ni][1] += s1 * pacc[mi][ni][1];
                        acc[mi][ni][2] += s0 * pacc[mi][ni][2];
                        acc[mi][ni][3] += s1 * pacc[mi][ni][3];
                        pacc[mi][ni][0] = 0.0f; pacc[mi][ni][1] = 0.0f;
                        pacc[mi][ni][2] = 0.0f; pacc[mi][ni][3] = 0.0f;
                    }
                }
            }
        }
    }

    const int lr = lid >> 2;
#pragma unroll
    for (int mi = 0; mi < 2; mi++) {
#pragma unroll
        for (int half = 0; half < 2; half++) {
            int row = m0 + wm + mi * 16 + half * 8 + lr;
            if (row < cnt) {
                int gs = base + row;
                float w = g_slot_w[gs];
                float* dst = g_outslot + (size_t)gs * HD + n0 + wn + lc;
#pragma unroll
                for (int ni = 0; ni < 4; ni++) {
                    float2 v = make_float2(acc[mi][ni][half * 2] * w,
                                           acc[mi][ni][half * 2 + 1] * w);
                    *(float2*)(dst + ni * 8) = v;
                }
            }
        }
    }
}

#define SMEM2 (2 * STAGE_BYTES + 32 * 128 * 4 + SCHED2 * 4 + 96)

// ---------------- combine: out[t] = outslot[s0] + outslot[s1] --------------
__global__ void k_combine(float* __restrict__ out) {
    int t = blockIdx.y;
    int n = blockIdx.x * 256 + threadIdx.x;
    int s0 = g_token_slot[t * 2 + 0];
    int s1 = g_token_slot[t * 2 + 1];
    out[(size_t)t * HD + n] = g_outslot[(size_t)s0 * HD + n] +
                              g_outslot[(size_t)s1 * HD + n];
}

// ---------------- launch ----------------------------------------------------
extern "C" void kernel_launch(void* const* d_in, const int* in_sizes, int n_in,
                              void* d_out, int out_size) {
    const float* x      = (const float*)d_in[0];
    const float* logits = (const float*)d_in[1];
    const int*   w13_q  = (const int*)  d_in[2];
    const int*   w2_q   = (const int*)  d_in[3];
    const float* w13_s  = (const float*)d_in[4];
    const float* w2_s   = (const float*)d_in[5];
    const int*   w13_g  = (const int*)  d_in[6];
    const int*   w2_g   = (const int*)  d_in[7];
    float* out = (float*)d_out;
    (void)in_sizes; (void)n_in; (void)out_size;

    static int s_attr_done = 0;
    if (!s_attr_done) {
        cudaFuncSetAttribute(k_gemm1,
                             cudaFuncAttributeMaxDynamicSharedMemorySize, SMEM1);
        cudaFuncSetAttribute(k_gemm2,
                             cudaFuncAttributeMaxDynamicSharedMemorySize, SMEM2);
        s_attr_done = 1;
    }

    // launch order: gemm1 is our launch index 3 -> the one ncu captures
    k_route<<<17, 256>>>(logits, w13_g, w2_g);                 // 0
    k_split_w13<<<dim3(128, NEXP), 256>>>(w13_q);              // 1
    k_split_x<<<(NSLOT * (K13P / 8)) / 256, 256>>>(x);         // 2

    // GEMM1 (+fused silu): y = K2P/64 = 72 permuted-j tiles
    k_gemm1<<<dim3(NTILES, K2P / 64), GTHREADS, SMEM1>>>(w13_s); // 3

    k_split_w2<<<dim3(128, NEXP), 256>>>(w2_q);                // 4

    // GEMM2: outslot = act @ q2^T (y = 8 n-tiles)
    k_gemm2<<<dim3(NTILES, HD / 128), GTHREADS, SMEM2>>>(w2_s); // 5

    k_combine<<<dim3(HD / 256, T_TOK), 256>>>(out);            // 6
}

// round 14
// speedup vs baseline: 1.1582x; 1.1582x over previous
#include <cuda_runtime.h>
#include <cuda_bf16.h>
#include <cstdint>

// Problem constants (fixed by setup_inputs)
#define T_TOK 2048
#define NEXP  8
#define HD    1024
#define ID    4096
#define NSLOT 4096
#define PADROWS (NSLOT + 256)
#define NTILES  72              // max m-tiles of 64 over experts

// permuted-k geometry: groups padded to 16, totals padded to 64
#define K13P   1152             // >= 1024 + 8*15, mult of 64
#define K2P    4608             // >= 4096 + 32*15, mult of 64
#define SCHED13 72              // 16-step entries
#define SCHED2  288

// ---------------- scratch (static device globals; no allocation) -----------
__device__ int   g_counts[NEXP];
__device__ int   g_base[NEXP];
__device__ int   g_slot_tok[NSLOT];
__device__ int   g_slot_e[NSLOT];
__device__ float g_slot_w[NSLOT];
__device__ int   g_token_slot[NSLOT];
__device__ int   g_tile_e[NTILES];
__device__ int   g_tile_m0[NTILES];

__device__ int   g_perm13[NEXP * K13P];
__device__ int   g_perm2 [NEXP * K2P];
__device__ int   g_sched13[NEXP * SCHED13];   // gid | 0x100 flush flag
__device__ int   g_sched2 [NEXP * SCHED2];
__device__ int   g_nch13[NEXP];
__device__ int   g_nch2 [NEXP];

// exact-integer weights (bf16 of q-8), k-permuted, [e][n][k']
__device__ __align__(256) __nv_bfloat16 g_q13p[(size_t)NEXP * 2 * ID * K13P];
__device__ __align__(256) __nv_bfloat16 g_q2p [(size_t)NEXP * HD * K2P];
// hi/lo split activations, k-permuted per slot's expert
__device__ __align__(256) __nv_bfloat16 g_xah [(size_t)PADROWS * K13P];
__device__ __align__(256) __nv_bfloat16 g_xal [(size_t)PADROWS * K13P];
__device__ __align__(256) __nv_bfloat16 g_acth[(size_t)PADROWS * K2P];
__device__ __align__(256) __nv_bfloat16 g_actl[(size_t)PADROWS * K2P];

__device__ __align__(256) float g_h[(size_t)NSLOT * 2 * ID];    // gemm1 out fp32
__device__ __align__(256) float g_outslot[(size_t)NSLOT * HD];  // gemm2 out fp32

// ---------------- helpers ---------------------------------------------------
__device__ __forceinline__ uint32_t smem_u32(const void* p) {
    uint32_t a;
    asm("{ .reg .u64 t; cvta.to.shared.u64 t, %1; cvt.u32.u64 %0, t; }"
        : "=r"(a) : "l"(p));
    return a;
}
__device__ __forceinline__ void ldsm4(uint32_t* r, uint32_t a) {
    asm volatile("ldmatrix.sync.aligned.m8n8.x4.shared.b16 {%0,%1,%2,%3}, [%4];"
                 : "=r"(r[0]), "=r"(r[1]), "=r"(r[2]), "=r"(r[3]) : "r"(a));
}
__device__ __forceinline__ void cpasync16(uint32_t saddr, const void* gaddr) {
    asm volatile("cp.async.cg.shared.global [%0], [%1], 16;"
                 :: "r"(saddr), "l"(gaddr) : "memory");
}
#define CP_COMMIT() asm volatile("cp.async.commit_group;" ::: "memory")
#define CP_WAIT1()  asm volatile("cp.async.wait_group 1;" ::: "memory")

__device__ __forceinline__ void mma16816(float* d, const uint32_t* a,
                                         uint32_t b0, uint32_t b1) {
    asm volatile(
        "mma.sync.aligned.m16n8k16.row.col.f32.bf16.bf16.f32 "
        "{%0,%1,%2,%3}, {%4,%5,%6,%7}, {%8,%9}, {%0,%1,%2,%3};"
        : "+f"(d[0]), "+f"(d[1]), "+f"(d[2]), "+f"(d[3])
        : "r"(a[0]), "r"(a[1]), "r"(a[2]), "r"(a[3]), "r"(b0), "r"(b1));
}
__device__ __forceinline__ void split2(float v, __nv_bfloat16& h, __nv_bfloat16& l) {
    h = __float2bfloat16(v);
    l = __float2bfloat16(v - __bfloat162float(h));
}

// ---------------- routing + permutation build (grid = 17 blocks) -----------
__global__ void k_route(const float* __restrict__ logits,
                        const int* __restrict__ gi13,
                        const int* __restrict__ gi2) {
    const int tid = threadIdx.x;
    if (blockIdx.x == 0) {
        __shared__ int   csh[NEXP];
        __shared__ int   cur[NEXP];
        __shared__ int   te[NSLOT];
        __shared__ float tw[NSLOT];
        if (tid < NEXP) csh[tid] = 0;
        __syncthreads();
        for (int t = tid; t < T_TOK; t += 256) {
            float l[NEXP];
#pragma unroll
            for (int e = 0; e < NEXP; e++) l[e] = logits[t * NEXP + e];
            int i1 = 0; float m1 = l[0];
            int i2 = -1; float m2 = -3.0e38f;
#pragma unroll
            for (int e = 1; e < NEXP; e++) {
                if (l[e] > m1) { m2 = m1; i2 = i1; m1 = l[e]; i1 = e; }
                else if (l[e] > m2) { m2 = l[e]; i2 = e; }
            }
            float r  = expf(m2 - m1);
            float w1 = 1.0f / (1.0f + r);
            float w2 = r * w1;
            te[t * 2 + 0] = i1;  te[t * 2 + 1] = i2;
            tw[t * 2 + 0] = w1;  tw[t * 2 + 1] = w2;
            atomicAdd(&csh[i1], 1);
            atomicAdd(&csh[i2], 1);
        }
        __syncthreads();
        if (tid == 0) {
            int acc = 0;
            for (int e = 0; e < NEXP; e++) {
                g_counts[e] = csh[e];
                g_base[e]   = acc;
                cur[e]      = acc;
                acc += csh[e];
            }
            int nt = 0;
            for (int e = 0; e < NEXP; e++)
                for (int m0 = 0; m0 < csh[e]; m0 += 64) {
                    g_tile_e[nt]  = e;
                    g_tile_m0[nt] = m0;
                    nt++;
                }
            for (; nt < NTILES; nt++) g_tile_e[nt] = -1;
        }
        __syncthreads();
        for (int t = tid; t < T_TOK; t += 256) {
#pragma unroll
            for (int j = 0; j < 2; j++) {
                int e   = te[t * 2 + j];
                int pos = atomicAdd(&cur[e], 1);
                g_slot_tok[pos]         = t;
                g_slot_e[pos]           = e;
                g_slot_w[pos]           = tw[t * 2 + j];
                g_token_slot[t * 2 + j] = pos;
            }
        }
    } else {
        // permutation builder
        const int pb  = blockIdx.x - 1;     // 0..15
        const int mat = pb >> 3;            // 0: w13, 1: w2
        const int e   = pb & 7;
        const int K   = mat ? ID : HD;
        const int G   = mat ? 32 : 8;
        const int KP  = mat ? K2P : K13P;
        const int SC  = mat ? SCHED2 : SCHED13;
        const int* gi = mat ? (gi2 + e * ID) : (gi13 + e * HD);
        int* perm  = mat ? (g_perm2 + e * K2P)   : (g_perm13 + e * K13P);
        int* sched = mat ? (g_sched2 + e * SCHED2) : (g_sched13 + e * SCHED13);

        __shared__ int lh[256 * 32];        // per-thread local hist
        __shared__ int gstart[33];
        const int perth = K / 256;          // 4 or 16
        const int kb = tid * perth;
        for (int g = 0; g < G; g++) lh[tid * G + g] = 0;
        __syncthreads();
        for (int i = 0; i < perth; i++) lh[tid * G + gi[kb + i]]++;
        __syncthreads();
        if (tid == 0) {
            int acc = 0, step = 0;
            for (int g = 0; g < G; g++) {
                int c = 0;
                for (int t = 0; t < 256; t++) c += lh[t * G + g];
                gstart[g] = acc;
                int stp = (c + 15) >> 4;
                for (int s = 0; s < stp; s++)
                    sched[step++] = g | ((s == stp - 1) ? 0x100 : 0);
                acc += stp << 4;
            }
            int nch = (step + 3) >> 2;
            if (mat) g_nch2[e] = nch; else g_nch13[e] = nch;
            for (; step < nch * 4; step++) sched[step] = 0;
            for (; step < SC; step++) sched[step] = 0;
        }
        __syncthreads();
        if (tid < G) {
            int off = gstart[tid];
            for (int t = 0; t < 256; t++) {
                int c = lh[t * G + tid];
                lh[t * G + tid] = off;
                off += c;
            }
        }
        __syncthreads();
        for (int i = tid; i < KP; i += 256) perm[i] = -1;
        __syncthreads();
        for (int i = 0; i < perth; i++) {
            int k = kb + i;
            int g = gi[k];
            perm[lh[tid * G + g]++] = k;
        }
    }
}

// ---------------- prolog: build exact-int bf16 weight matrices -------------
__global__ void k_split_w13(const int* __restrict__ qw) {
    __shared__ int sq[128 * 65];            // [kp][nn], padded stride
    __shared__ int sperm[K13P];
    const int e  = blockIdx.y;
    const int n0 = blockIdx.x * 64;
    const int tid = threadIdx.x;
    for (int i = tid; i < 128 * 64; i += 256) {
        int kp = i >> 6, nn = i & 63;
        sq[kp * 65 + nn] = qw[((size_t)e * 128 + kp) * 8192 + n0 + nn];
    }
    for (int i = tid; i < K13P; i += 256) sperm[i] = g_perm13[e * K13P + i];
    __syncthreads();
    for (int c = tid; c < 64 * (K13P / 8); c += 256) {
        int oct = c % (K13P / 8);
        int nn  = c / (K13P / 8);
        alignas(16) __nv_bfloat16 out[8];
        int4 p0 = *(const int4*)&sperm[oct * 8];
        int4 p1 = *(const int4*)&sperm[oct * 8 + 4];
        int pk[8] = {p0.x, p0.y, p0.z, p0.w, p1.x, p1.y, p1.z, p1.w};
#pragma unroll
        for (int j = 0; j < 8; j++) {
            int k = pk[j];
            int v = (k < 0) ? 0 : (((sq[(k >> 3) * 65 + nn] >> ((k & 7) * 4)) & 15) - 8);
            out[j] = __float2bfloat16((float)v);
        }
        *(uint4*)(g_q13p + ((size_t)e * 8192 + n0 + nn) * K13P + oct * 8) = *(uint4*)out;
    }
}

__global__ void k_split_w2(const int* __restrict__ qw) {
    __shared__ int sq[512 * 9];             // [kp][nn], padded
    __shared__ int sperm[K2P];
    const int e  = blockIdx.y;
    const int n0 = blockIdx.x * 8;
    const int tid = threadIdx.x;
    for (int i = tid; i < 512 * 8; i += 256) {
        int kp = i >> 3, nn = i & 7;
        sq[kp * 9 + nn] = qw[((size_t)e * 512 + kp) * 1024 + n0 + nn];
    }
    for (int i = tid; i < K2P; i += 256) sperm[i] = g_perm2[e * K2P + i];
    __syncthreads();
    for (int c = tid; c < 8 * (K2P / 8); c += 256) {
        int oct = c % (K2P / 8);
        int nn  = c / (K2P / 8);
        alignas(16) __nv_bfloat16 out[8];
        int4 p0 = *(const int4*)&sperm[oct * 8];
        int4 p1 = *(const int4*)&sperm[oct * 8 + 4];
        int pk[8] = {p0.x, p0.y, p0.z, p0.w, p1.x, p1.y, p1.z, p1.w};
#pragma unroll
        for (int j = 0; j < 8; j++) {
            int k = pk[j];
            int v = (k < 0) ? 0 : (((sq[(k >> 3) * 9 + nn] >> ((k & 7) * 4)) & 15) - 8);
            out[j] = __float2bfloat16((float)v);
        }
        *(uint4*)(g_q2p + ((size_t)e * 1024 + n0 + nn) * K2P + oct * 8) = *(uint4*)out;
    }
}

// ---------------- prolog: gather x (permuted k), split hi/lo ----------------
__global__ void k_split_x(const float* __restrict__ x) {
    int id  = blockIdx.x * 256 + threadIdx.x;
    int oct = id % (K13P / 8);
    int s   = id / (K13P / 8);
    int e   = g_slot_e[s];
    int tok = g_slot_tok[s];
    const int* pm = g_perm13 + e * K13P + oct * 8;
    alignas(16) __nv_bfloat16 h[8], l[8];
#pragma unroll
    for (int j = 0; j < 8; j++) {
        int k = pm[j];
        float v = (k < 0) ? 0.0f : x[(size_t)tok * HD + k];
        split2(v, h[j], l[j]);
    }
    size_t o = (size_t)s * K13P + oct * 8;
    *(uint4*)(g_xah + o) = *(uint4*)h;
    *(uint4*)(g_xal + o) = *(uint4*)l;
}

// ---------------- activation: silu(gate)*up, permuted k2, split hi/lo ------
__global__ void k_act() {
    __shared__ float sa[ID];
    const int s   = blockIdx.x;
    const int tid = threadIdx.x;
    const int e   = g_slot_e[s];
    const float* gp = g_h + (size_t)s * (2 * ID);
    for (int i = tid; i < ID; i += 256) {
        float g = gp[i];
        float u = gp[ID + i];
        sa[i] = g / (1.0f + expf(-g)) * u;
    }
    __syncthreads();
    for (int oct = tid; oct < K2P / 8; oct += 256) {
        const int* pm = g_perm2 + e * K2P + oct * 8;
        alignas(16) __nv_bfloat16 h[8], l[8];
#pragma unroll
        for (int j = 0; j < 8; j++) {
            int k = pm[j];
            float v = (k < 0) ? 0.0f : sa[k];
            split2(v, h[j], l[j]);
        }
        size_t o = (size_t)s * K2P + oct * 8;
        *(uint4*)(g_acth + o) = *(uint4*)h;
        *(uint4*)(g_actl + o) = *(uint4*)l;
    }
}

// ---------------- HMMA 2-term exact-int GEMM (3-stage cp.async) ------------
// Block 64x128, BK=64, 256 thr / 8 warps (32x32 warp tiles), 3-stage cp.async
// (wait_group 1 -> consumed stage completed two chunks ago; copy latency off
// the critical path), 2 CTAs/SM. Terms: xh*q + xl*q into one pacc; flush
// acc += s[g][n]*pacc at group-end steps.  GEMM1 keeps the scale tile in
// smem; GEMM2 reads flush scales straight from gmem (fp32, L2-hot) to keep
// 3 stages x 2 CTAs under the smem ceiling.
#define PITCH_B 144
#define AMAT    (64 * PITCH_B)               // 9216
#define BMAT    (128 * PITCH_B)              // 18432
#define STAGE_BYTES (2 * AMAT + BMAT)        // 36864
#define GTHREADS    256

template<int KP, int G, int NSC, bool G2>
__global__ __launch_bounds__(GTHREADS, 2) void k_gemm(const float* __restrict__ sc) {
    extern __shared__ __align__(128) char smem[];
    const int e = g_tile_e[blockIdx.x];
    if (e < 0) return;
    const int m0   = g_tile_m0[blockIdx.x];
    const int cnt  = g_counts[e];
    const int base = g_base[e];
    const int n0   = blockIdx.y * 128;
    const int tid  = threadIdx.x;
    const int lid  = tid & 31;
    const int wid  = tid >> 5;
    const int wm   = (wid >> 2) * 32;   // warp m offset: 0 / 32
    const int wn   = (wid & 3) * 32;    // warp n offset: 0..96

    const __nv_bfloat16* Axh;
    const __nv_bfloat16* Axl;
    const __nv_bfloat16* Bq;
    const int* schedg;
    int nch;
    if constexpr (G2) {
        Axh = g_acth + (size_t)(base + m0) * KP;
        Axl = g_actl + (size_t)(base + m0) * KP;
        Bq  = g_q2p + (size_t)e * HD * KP + (size_t)n0 * KP;
        schedg = g_sched2 + e * SCHED2;
        nch = g_nch2[e];
    } else {
        Axh = g_xah + (size_t)(base + m0) * KP;
        Axl = g_xal + (size_t)(base + m0) * KP;
        Bq  = g_q13p + (size_t)e * 2 * ID * KP + (size_t)n0 * KP;
        schedg = g_sched13 + e * SCHED13;
        nch = g_nch13[e];
    }

    const uint32_t sbase = smem_u32(smem);
    float* stile = (float*)(smem + 3 * STAGE_BYTES);       // [G][128], gemm1 only
    int* ssched;
    if constexpr (G2) ssched = (int*)(smem + 3 * STAGE_BYTES);
    else              ssched = (int*)(smem + 3 * STAGE_BYTES + G * 128 * 4);

    if constexpr (!G2) {
        // preload scale tile (plain LDG/STS; visible after first barrier)
        for (int i = tid; i < G * 128; i += GTHREADS) {
            int g = i >> 7, j = i & 127;
            stile[i] = sc[((size_t)e * G + g) * NSC + n0 + j];
        }
    }
    for (int i = tid; i < nch * 4; i += GTHREADS) ssched[i] = schedg[i];

    float acc[2][4][4], pacc[2][4][4];
#pragma unroll
    for (int i = 0; i < 2; i++)
#pragma unroll
        for (int j = 0; j < 4; j++)
#pragma unroll
            for (int k = 0; k < 4; k++) { acc[i][j][k] = 0.0f; pacc[i][j][k] = 0.0f; }

    const uint32_t a_row  = (uint32_t)(lid & 15);
    const uint32_t a_koff = (uint32_t)((lid >> 4) * 16);
    const uint32_t b_row  = (uint32_t)(((lid >> 4) & 1) * 8 + (lid & 7));
    const uint32_t b_koff = (uint32_t)(((lid >> 3) & 1) * 16);
    const int lc = (lid & 3) * 2;

    // stage fill: 2048 16B chunks (A: 2x64x8 = 1024, B: 128x8 = 1024)
    auto issue_stage = [&](uint32_t sb, int k0) {
#pragma unroll
        for (int it = 0; it < 8; it++) {
            int j = it * GTHREADS + tid;
            const __nv_bfloat16* src;
            uint32_t dst;
            if (j < 1024) {
                int mat = j >> 9, jj = j & 511;
                int r = jj >> 3, c = jj & 7;
                src = (mat ? Axl : Axh) + (size_t)r * KP + k0 + c * 8;
                dst = (uint32_t)(mat * AMAT + r * PITCH_B + c * 16);
            } else {
                int jb = j - 1024;
                int r = jb >> 3, c = jb & 7;
                src = Bq + (size_t)r * KP + k0 + c * 8;
                dst = (uint32_t)(2 * AMAT + r * PITCH_B + c * 16);
            }
            cpasync16(sb + dst, src);
        }
    };

    // prologue: stages 0 and 1 in flight
    issue_stage(sbase, 0);
    CP_COMMIT();
    if (nch > 1) issue_stage(sbase + STAGE_BYTES, 64);
    CP_COMMIT();

    for (int ch = 0; ch < nch; ch++) {
        CP_WAIT1();                 // stage ch complete (ch+1 may be in flight)
        __syncthreads();
        const uint32_t buf = sbase + (uint32_t)((ch % 3) * STAGE_BYTES);

        // issue stage ch+2 (its buffer was consumed in iter ch-1)
        if (ch + 2 < nch)
            issue_stage(sbase + (uint32_t)(((ch + 2) % 3) * STAGE_BYTES),
                        (ch + 2) * 64);
        CP_COMMIT();                // keep group count in lockstep

#pragma unroll
        for (int s = 0; s < 4; s++) {
            uint32_t ah[2][4], al[2][4];
#pragma unroll
            for (int mi = 0; mi < 2; mi++) {
                uint32_t ra = buf + (uint32_t)((wm + mi * 16 + a_row) * PITCH_B)
                                  + (uint32_t)(s * 32) + a_koff;
                ldsm4(ah[mi], ra);
                ldsm4(al[mi], ra + AMAT);
            }
            uint32_t bq[2][4];
#pragma unroll
            for (int p = 0; p < 2; p++) {
                uint32_t rb = buf + 2u * AMAT
                                  + (uint32_t)((wn + p * 16 + b_row) * PITCH_B)
                                  + (uint32_t)(s * 32) + b_koff;
                ldsm4(bq[p], rb);
            }
#pragma unroll
            for (int ni = 0; ni < 4; ni++) {
                uint32_t b0 = bq[ni >> 1][(ni & 1) * 2];
                uint32_t b1 = bq[ni >> 1][(ni & 1) * 2 + 1];
#pragma unroll
                for (int mi = 0; mi < 2; mi++) {
                    mma16816(pacc[mi][ni], ah[mi], b0, b1);
                    mma16816(pacc[mi][ni], al[mi], b0, b1);
                }
            }
            // group-boundary flush: acc += s[g][n] * pacc
            int ent = ssched[ch * 4 + s];
            if (ent & 0x100) {
#pragma unroll
                for (int ni = 0; ni < 4; ni++) {
                    float s0, s1;
                    if constexpr (G2) {
                        const float* sp = sc + ((size_t)e * G + (ent & 0xFF)) * NSC
                                             + n0 + wn + ni * 8 + lc;
                        float2 sv = __ldg((const float2*)sp);
                        s0 = sv.x; s1 = sv.y;
                    } else {
                        const float* srow = stile + (ent & 0xFF) * 128;
                        s0 = srow[wn + ni * 8 + lc];
                        s1 = srow[wn + ni * 8 + lc + 1];
                    }
#pragma unroll
                    for (int mi = 0; mi < 2; mi++) {
                        acc[mi][ni][0] += s0 * pacc[mi][ni][0];
                        acc[mi][ni][1] += s1 * pacc[mi][ni][1];
                        acc[mi][ni][2] += s0 * pacc[mi][ni][2];
                        acc[mi][ni][3] += s1 * pacc[mi][ni][3];
                        pacc[mi][ni][0] = 0.0f; pacc[mi][ni][1] = 0.0f;
                        pacc[mi][ni][2] = 0.0f; pacc[mi][ni][3] = 0.0f;
                    }
                }
            }
        }
    }

    // epilogue: acc (fully scaled) -> global fp32
    const int lr = lid >> 2;
#pragma unroll
    for (int mi = 0; mi < 2; mi++) {
#pragma unroll
        for (int half = 0; half < 2; half++) {
            int row = m0 + wm + mi * 16 + half * 8 + lr;
            if (row < cnt) {
                int gs = base + row;
                if constexpr (!G2) {
                    float* dst = g_h + (size_t)gs * (2 * ID) + n0 + wn + lc;
#pragma unroll
                    for (int ni = 0; ni < 4; ni++) {
                        float2 v = make_float2(acc[mi][ni][half * 2],
                                               acc[mi][ni][half * 2 + 1]);
                        *(float2*)(dst + ni * 8) = v;
                    }
                } else {
                    float w = g_slot_w[gs];
                    float* dst = g_outslot + (size_t)gs * HD + n0 + wn + lc;
#pragma unroll
                    for (int ni = 0; ni < 4; ni++) {
                        float2 v = make_float2(acc[mi][ni][half * 2] * w,
                                               acc[mi][ni][half * 2 + 1] * w);
                        *(float2*)(dst + ni * 8) = v;
                    }
                }
            }
        }
    }
}

#define SMEM1 (3 * STAGE_BYTES + 8 * 128 * 4 + SCHED13 * 4)   // 114,976
#define SMEM2 (3 * STAGE_BYTES + SCHED2 * 4)                  // 111,744

// ---------------- combine: out[t] = outslot[s0] + outslot[s1] --------------
__global__ void k_combine(float* __restrict__ out) {
    int t = blockIdx.y;
    int n = blockIdx.x * 256 + threadIdx.x;
    int s0 = g_token_slot[t * 2 + 0];
    int s1 = g_token_slot[t * 2 + 1];
    out[(size_t)t * HD + n] = g_outslot[(size_t)s0 * HD + n] +
                              g_outslot[(size_t)s1 * HD + n];
}

// ---------------- launch ----------------------------------------------------
extern "C" void kernel_launch(void* const* d_in, const int* in_sizes, int n_in,
                              void* d_out, int out_size) {
    const float* x      = (const float*)d_in[0];
    const float* logits = (const float*)d_in[1];
    const int*   w13_q  = (const int*)  d_in[2];
    const int*   w2_q   = (const int*)  d_in[3];
    const float* w13_s  = (const float*)d_in[4];
    const float* w2_s   = (const float*)d_in[5];
    const int*   w13_g  = (const int*)  d_in[6];
    const int*   w2_g   = (const int*)  d_in[7];
    float* out = (float*)d_out;
    (void)in_sizes; (void)n_in; (void)out_size;

    static int s_attr_done = 0;
    if (!s_attr_done) {
        cudaFuncSetAttribute(k_gemm<K13P, 8, 8192, false>,
                             cudaFuncAttributeMaxDynamicSharedMemorySize, SMEM1);
        cudaFuncSetAttribute(k_gemm<K2P, 32, 1024, true>,
                             cudaFuncAttributeMaxDynamicSharedMemorySize, SMEM2);
        s_attr_done = 1;
    }

    // launch order: gemm1 is our launch index 3 -> the one ncu captures
    k_route<<<17, 256>>>(logits, w13_g, w2_g);                 // 0
    k_split_w13<<<dim3(128, NEXP), 256>>>(w13_q);              // 1
    k_split_x<<<(NSLOT * (K13P / 8)) / 256, 256>>>(x);         // 2

    // GEMM1: h = x @ q13^T with group-scale flush (y = 64 n-tiles)
    k_gemm<K13P, 8, 8192, false>
        <<<dim3(NTILES, 2 * ID / 128), GTHREADS, SMEM1>>>(w13_s); // 3

    k_split_w2<<<dim3(128, NEXP), 256>>>(w2_q);                // 4
    k_act<<<NSLOT, 256>>>();                                   // 5

    // GEMM2: outslot = act @ q2^T (y = 8 n-tiles)
    k_gemm<K2P, 32, 1024, true>
        <<<dim3(NTILES, HD / 128), GTHREADS, SMEM2>>>(w2_s);   // 6

    k_combine<<<dim3(HD / 256, T_TOK), 256>>>(out);            // 7
}

// round 15
// speedup vs baseline: 1.1676x; 1.0081x over previous
#include <cuda_runtime.h>
#include <cuda_bf16.h>
#include <cstdint>

// Problem constants (fixed by setup_inputs)
#define T_TOK 2048
#define NEXP  8
#define HD    1024
#define ID    4096
#define NSLOT 4096
#define PADROWS (NSLOT + 256)
#define NTILES  72              // max m-tiles of 64 over experts

// permuted-k geometry: groups padded to 16, totals padded to 64
#define K13P   1152             // >= 1024 + 8*15, mult of 64
#define K2P    4608             // >= 4096 + 32*15, mult of 64
#define SCHED13 72              // 16-step entries
#define SCHED2  288

// ---------------- scratch (static device globals; no allocation) -----------
__device__ int   g_counts[NEXP];
__device__ int   g_base[NEXP];
__device__ int   g_slot_tok[NSLOT];
__device__ int   g_slot_e[NSLOT];
__device__ float g_slot_w[NSLOT];
__device__ int   g_token_slot[NSLOT];
__device__ int   g_tile_e[NTILES];
__device__ int   g_tile_m0[NTILES];

__device__ int   g_perm13[NEXP * K13P];
__device__ int   g_perm2 [NEXP * K2P];
__device__ int   g_sched13[NEXP * SCHED13];   // gid | 0x100 flush flag
__device__ int   g_sched2 [NEXP * SCHED2];
__device__ int   g_nch13[NEXP];
__device__ int   g_nch2 [NEXP];

// exact-integer weights (bf16 of q-8), k-permuted, [e][n][k']
__device__ __align__(256) __nv_bfloat16 g_q13p[(size_t)NEXP * 2 * ID * K13P];
__device__ __align__(256) __nv_bfloat16 g_q2p [(size_t)NEXP * HD * K2P];
// hi/lo split activations, k-permuted per slot's expert
__device__ __align__(256) __nv_bfloat16 g_xah [(size_t)PADROWS * K13P];
__device__ __align__(256) __nv_bfloat16 g_xal [(size_t)PADROWS * K13P];
__device__ __align__(256) __nv_bfloat16 g_acth[(size_t)PADROWS * K2P];
__device__ __align__(256) __nv_bfloat16 g_actl[(size_t)PADROWS * K2P];

__device__ __align__(256) float g_h[(size_t)NSLOT * 2 * ID];    // gemm1 out fp32
__device__ __align__(256) float g_outslot[(size_t)NSLOT * HD];  // gemm2 out fp32

// ---------------- helpers ---------------------------------------------------
__device__ __forceinline__ uint32_t smem_u32(const void* p) {
    uint32_t a;
    asm("{ .reg .u64 t; cvta.to.shared.u64 t, %1; cvt.u32.u64 %0, t; }"
        : "=r"(a) : "l"(p));
    return a;
}
__device__ __forceinline__ void ldsm4(uint32_t* r, uint32_t a) {
    asm volatile("ldmatrix.sync.aligned.m8n8.x4.shared.b16 {%0,%1,%2,%3}, [%4];"
                 : "=r"(r[0]), "=r"(r[1]), "=r"(r[2]), "=r"(r[3]) : "r"(a));
}
__device__ __forceinline__ void cpasync16(uint32_t saddr, const void* gaddr) {
    asm volatile("cp.async.cg.shared.global [%0], [%1], 16;"
                 :: "r"(saddr), "l"(gaddr) : "memory");
}
#define CP_COMMIT() asm volatile("cp.async.commit_group;" ::: "memory")
#define CP_WAIT1()  asm volatile("cp.async.wait_group 1;" ::: "memory")

// NOTE: non-volatile — pure dataflow op; lets nvcc/ptxas schedule MMAs to
// cover writeback latency (the volatile version pinned program order and
// exposed the pacc RAW chain).
__device__ __forceinline__ void mma16816(float* d, const uint32_t* a,
                                         uint32_t b0, uint32_t b1) {
    asm("mma.sync.aligned.m16n8k16.row.col.f32.bf16.bf16.f32 "
        "{%0,%1,%2,%3}, {%4,%5,%6,%7}, {%8,%9}, {%0,%1,%2,%3};"
        : "+f"(d[0]), "+f"(d[1]), "+f"(d[2]), "+f"(d[3])
        : "r"(a[0]), "r"(a[1]), "r"(a[2]), "r"(a[3]), "r"(b0), "r"(b1));
}
__device__ __forceinline__ void split2(float v, __nv_bfloat16& h, __nv_bfloat16& l) {
    h = __float2bfloat16(v);
    l = __float2bfloat16(v - __bfloat162float(h));
}

// ---------------- routing + permutation build (grid = 17 blocks) -----------
__global__ void k_route(const float* __restrict__ logits,
                        const int* __restrict__ gi13,
                        const int* __restrict__ gi2) {
    const int tid = threadIdx.x;
    if (blockIdx.x == 0) {
        __shared__ int   csh[NEXP];
        __shared__ int   cur[NEXP];
        __shared__ int   te[NSLOT];
        __shared__ float tw[NSLOT];
        if (tid < NEXP) csh[tid] = 0;
        __syncthreads();
        for (int t = tid; t < T_TOK; t += 256) {
            float l[NEXP];
#pragma unroll
            for (int e = 0; e < NEXP; e++) l[e] = logits[t * NEXP + e];
            int i1 = 0; float m1 = l[0];
            int i2 = -1; float m2 = -3.0e38f;
#pragma unroll
            for (int e = 1; e < NEXP; e++) {
                if (l[e] > m1) { m2 = m1; i2 = i1; m1 = l[e]; i1 = e; }
                else if (l[e] > m2) { m2 = l[e]; i2 = e; }
            }
            float r  = expf(m2 - m1);
            float w1 = 1.0f / (1.0f + r);
            float w2 = r * w1;
            te[t * 2 + 0] = i1;  te[t * 2 + 1] = i2;
            tw[t * 2 + 0] = w1;  tw[t * 2 + 1] = w2;
            atomicAdd(&csh[i1], 1);
            atomicAdd(&csh[i2], 1);
        }
        __syncthreads();
        if (tid == 0) {
            int acc = 0;
            for (int e = 0; e < NEXP; e++) {
                g_counts[e] = csh[e];
                g_base[e]   = acc;
                cur[e]      = acc;
                acc += csh[e];
            }
            int nt = 0;
            for (int e = 0; e < NEXP; e++)
                for (int m0 = 0; m0 < csh[e]; m0 += 64) {
                    g_tile_e[nt]  = e;
                    g_tile_m0[nt] = m0;
                    nt++;
                }
            for (; nt < NTILES; nt++) g_tile_e[nt] = -1;
        }
        __syncthreads();
        for (int t = tid; t < T_TOK; t += 256) {
#pragma unroll
            for (int j = 0; j < 2; j++) {
                int e   = te[t * 2 + j];
                int pos = atomicAdd(&cur[e], 1);
                g_slot_tok[pos]         = t;
                g_slot_e[pos]           = e;
                g_slot_w[pos]           = tw[t * 2 + j];
                g_token_slot[t * 2 + j] = pos;
            }
        }
    } else {
        // permutation builder
        const int pb  = blockIdx.x - 1;     // 0..15
        const int mat = pb >> 3;            // 0: w13, 1: w2
        const int e   = pb & 7;
        const int K   = mat ? ID : HD;
        const int G   = mat ? 32 : 8;
        const int KP  = mat ? K2P : K13P;
        const int SC  = mat ? SCHED2 : SCHED13;
        const int* gi = mat ? (gi2 + e * ID) : (gi13 + e * HD);
        int* perm  = mat ? (g_perm2 + e * K2P)   : (g_perm13 + e * K13P);
        int* sched = mat ? (g_sched2 + e * SCHED2) : (g_sched13 + e * SCHED13);

        __shared__ int lh[256 * 32];        // per-thread local hist
        __shared__ int gstart[33];
        const int perth = K / 256;          // 4 or 16
        const int kb = tid * perth;
        for (int g = 0; g < G; g++) lh[tid * G + g] = 0;
        __syncthreads();
        for (int i = 0; i < perth; i++) lh[tid * G + gi[kb + i]]++;
        __syncthreads();
        if (tid == 0) {
            int acc = 0, step = 0;
            for (int g = 0; g < G; g++) {
                int c = 0;
                for (int t = 0; t < 256; t++) c += lh[t * G + g];
                gstart[g] = acc;
                int stp = (c + 15) >> 4;
                for (int s = 0; s < stp; s++)
                    sched[step++] = g | ((s == stp - 1) ? 0x100 : 0);
                acc += stp << 4;
            }
            int nch = (step + 3) >> 2;
            if (mat) g_nch2[e] = nch; else g_nch13[e] = nch;
            for (; step < nch * 4; step++) sched[step] = 0;
            for (; step < SC; step++) sched[step] = 0;
        }
        __syncthreads();
        if (tid < G) {
            int off = gstart[tid];
            for (int t = 0; t < 256; t++) {
                int c = lh[t * G + tid];
                lh[t * G + tid] = off;
                off += c;
            }
        }
        __syncthreads();
        for (int i = tid; i < KP; i += 256) perm[i] = -1;
        __syncthreads();
        for (int i = 0; i < perth; i++) {
            int k = kb + i;
            int g = gi[k];
            perm[lh[tid * G + g]++] = k;
        }
    }
}

// ---------------- prolog: build exact-int bf16 weight matrices -------------
__global__ void k_split_w13(const int* __restrict__ qw) {
    __shared__ int sq[128 * 65];            // [kp][nn], padded stride
    __shared__ int sperm[K13P];
    const int e  = blockIdx.y;
    const int n0 = blockIdx.x * 64;
    const int tid = threadIdx.x;
    for (int i = tid; i < 128 * 64; i += 256) {
        int kp = i >> 6, nn = i & 63;
        sq[kp * 65 + nn] = qw[((size_t)e * 128 + kp) * 8192 + n0 + nn];
    }
    for (int i = tid; i < K13P; i += 256) sperm[i] = g_perm13[e * K13P + i];
    __syncthreads();
    for (int c = tid; c < 64 * (K13P / 8); c += 256) {
        int oct = c % (K13P / 8);
        int nn  = c / (K13P / 8);
        alignas(16) __nv_bfloat16 out[8];
        int4 p0 = *(const int4*)&sperm[oct * 8];
        int4 p1 = *(const int4*)&sperm[oct * 8 + 4];
        int pk[8] = {p0.x, p0.y, p0.z, p0.w, p1.x, p1.y, p1.z, p1.w};
#pragma unroll
        for (int j = 0; j < 8; j++) {
            int k = pk[j];
            int v = (k < 0) ? 0 : (((sq[(k >> 3) * 65 + nn] >> ((k & 7) * 4)) & 15) - 8);
            out[j] = __float2bfloat16((float)v);
        }
        *(uint4*)(g_q13p + ((size_t)e * 8192 + n0 + nn) * K13P + oct * 8) = *(uint4*)out;
    }
}

__global__ void k_split_w2(const int* __restrict__ qw) {
    __shared__ int sq[512 * 9];             // [kp][nn], padded
    __shared__ int sperm[K2P];
    const int e  = blockIdx.y;
    const int n0 = blockIdx.x * 8;
    const int tid = threadIdx.x;
    for (int i = tid; i < 512 * 8; i += 256) {
        int kp = i >> 3, nn = i & 7;
        sq[kp * 9 + nn] = qw[((size_t)e * 512 + kp) * 1024 + n0 + nn];
    }
    for (int i = tid; i < K2P; i += 256) sperm[i] = g_perm2[e * K2P + i];
    __syncthreads();
    for (int c = tid; c < 8 * (K2P / 8); c += 256) {
        int oct = c % (K2P / 8);
        int nn  = c / (K2P / 8);
        alignas(16) __nv_bfloat16 out[8];
        int4 p0 = *(const int4*)&sperm[oct * 8];
        int4 p1 = *(const int4*)&sperm[oct * 8 + 4];
        int pk[8] = {p0.x, p0.y, p0.z, p0.w, p1.x, p1.y, p1.z, p1.w};
#pragma unroll
        for (int j = 0; j < 8; j++) {
            int k = pk[j];
            int v = (k < 0) ? 0 : (((sq[(k >> 3) * 9 + nn] >> ((k & 7) * 4)) & 15) - 8);
            out[j] = __float2bfloat16((float)v);
        }
        *(uint4*)(g_q2p + ((size_t)e * 1024 + n0 + nn) * K2P + oct * 8) = *(uint4*)out;
    }
}

// ---------------- prolog: gather x (permuted k), split hi/lo ----------------
__global__ void k_split_x(const float* __restrict__ x) {
    int id  = blockIdx.x * 256 + threadIdx.x;
    int oct = id % (K13P / 8);
    int s   = id / (K13P / 8);
    int e   = g_slot_e[s];
    int tok = g_slot_tok[s];
    const int* pm = g_perm13 + e * K13P + oct * 8;
    alignas(16) __nv_bfloat16 h[8], l[8];
#pragma unroll
    for (int j = 0; j < 8; j++) {
        int k = pm[j];
        float v = (k < 0) ? 0.0f : x[(size_t)tok * HD + k];
        split2(v, h[j], l[j]);
    }
    size_t o = (size_t)s * K13P + oct * 8;
    *(uint4*)(g_xah + o) = *(uint4*)h;
    *(uint4*)(g_xal + o) = *(uint4*)l;
}

// ---------------- activation: silu(gate)*up, permuted k2, split hi/lo ------
__global__ void k_act() {
    __shared__ float sa[ID];
    const int s   = blockIdx.x;
    const int tid = threadIdx.x;
    const int e   = g_slot_e[s];
    const float* gp = g_h + (size_t)s * (2 * ID);
    for (int i = tid; i < ID; i += 256) {
        float g = gp[i];
        float u = gp[ID + i];
        sa[i] = g / (1.0f + expf(-g)) * u;
    }
    __syncthreads();
    for (int oct = tid; oct < K2P / 8; oct += 256) {
        const int* pm = g_perm2 + e * K2P + oct * 8;
        alignas(16) __nv_bfloat16 h[8], l[8];
#pragma unroll
        for (int j = 0; j < 8; j++) {
            int k = pm[j];
            float v = (k < 0) ? 0.0f : sa[k];
            split2(v, h[j], l[j]);
        }
        size_t o = (size_t)s * K2P + oct * 8;
        *(uint4*)(g_acth + o) = *(uint4*)h;
        *(uint4*)(g_actl + o) = *(uint4*)l;
    }
}

// ---------------- HMMA 2-term exact-int GEMM (3-stage cp.async) ------------
// Block 64x128, BK=64, 256 thr / 8 warps (32x32 warp tiles), 3-stage cp.async,
// 2 CTAs/SM.  Inner loop issues the 8 independent ah-MMAs first, then the 8
// al-MMAs: RAW distance on each pacc register group is 8 issue slots instead
// of 1, so MMA writeback latency is covered by independent work.
#define PITCH_B 144
#define AMAT    (64 * PITCH_B)               // 9216
#define BMAT    (128 * PITCH_B)              // 18432
#define STAGE_BYTES (2 * AMAT + BMAT)        // 36864
#define GTHREADS    256

template<int KP, int G, int NSC, bool G2>
__global__ __launch_bounds__(GTHREADS, 2) void k_gemm(const float* __restrict__ sc) {
    extern __shared__ __align__(128) char smem[];
    const int e = g_tile_e[blockIdx.x];
    if (e < 0) return;
    const int m0   = g_tile_m0[blockIdx.x];
    const int cnt  = g_counts[e];
    const int base = g_base[e];
    const int n0   = blockIdx.y * 128;
    const int tid  = threadIdx.x;
    const int lid  = tid & 31;
    const int wid  = tid >> 5;
    const int wm   = (wid >> 2) * 32;   // warp m offset: 0 / 32
    const int wn   = (wid & 3) * 32;    // warp n offset: 0..96

    const __nv_bfloat16* Axh;
    const __nv_bfloat16* Axl;
    const __nv_bfloat16* Bq;
    const int* schedg;
    int nch;
    if constexpr (G2) {
        Axh = g_acth + (size_t)(base + m0) * KP;
        Axl = g_actl + (size_t)(base + m0) * KP;
        Bq  = g_q2p + (size_t)e * HD * KP + (size_t)n0 * KP;
        schedg = g_sched2 + e * SCHED2;
        nch = g_nch2[e];
    } else {
        Axh = g_xah + (size_t)(base + m0) * KP;
        Axl = g_xal + (size_t)(base + m0) * KP;
        Bq  = g_q13p + (size_t)e * 2 * ID * KP + (size_t)n0 * KP;
        schedg = g_sched13 + e * SCHED13;
        nch = g_nch13[e];
    }

    const uint32_t sbase = smem_u32(smem);
    float* stile = (float*)(smem + 3 * STAGE_BYTES);       // [G][128], gemm1 only
    int* ssched;
    if constexpr (G2) ssched = (int*)(smem + 3 * STAGE_BYTES);
    else              ssched = (int*)(smem + 3 * STAGE_BYTES + G * 128 * 4);

    if constexpr (!G2) {
        for (int i = tid; i < G * 128; i += GTHREADS) {
            int g = i >> 7, j = i & 127;
            stile[i] = sc[((size_t)e * G + g) * NSC + n0 + j];
        }
    }
    for (int i = tid; i < nch * 4; i += GTHREADS) ssched[i] = schedg[i];

    float acc[2][4][4], pacc[2][4][4];
#pragma unroll
    for (int i = 0; i < 2; i++)
#pragma unroll
        for (int j = 0; j < 4; j++)
#pragma unroll
            for (int k = 0; k < 4; k++) { acc[i][j][k] = 0.0f; pacc[i][j][k] = 0.0f; }

    const uint32_t a_row  = (uint32_t)(lid & 15);
    const uint32_t a_koff = (uint32_t)((lid >> 4) * 16);
    const uint32_t b_row  = (uint32_t)(((lid >> 4) & 1) * 8 + (lid & 7));
    const uint32_t b_koff = (uint32_t)(((lid >> 3) & 1) * 16);
    const int lc = (lid & 3) * 2;

    // stage fill: 2048 16B chunks (A: 2x64x8 = 1024, B: 128x8 = 1024)
    auto issue_stage = [&](uint32_t sb, int k0) {
#pragma unroll
        for (int it = 0; it < 8; it++) {
            int j = it * GTHREADS + tid;
            const __nv_bfloat16* src;
            uint32_t dst;
            if (j < 1024) {
                int mat = j >> 9, jj = j & 511;
                int r = jj >> 3, c = jj & 7;
                src = (mat ? Axl : Axh) + (size_t)r * KP + k0 + c * 8;
                dst = (uint32_t)(mat * AMAT + r * PITCH_B + c * 16);
            } else {
                int jb = j - 1024;
                int r = jb >> 3, c = jb & 7;
                src = Bq + (size_t)r * KP + k0 + c * 8;
                dst = (uint32_t)(2 * AMAT + r * PITCH_B + c * 16);
            }
            cpasync16(sb + dst, src);
        }
    };

    // prologue: stages 0 and 1 in flight
    issue_stage(sbase, 0);
    CP_COMMIT();
    if (nch > 1) issue_stage(sbase + STAGE_BYTES, 64);
    CP_COMMIT();

    for (int ch = 0; ch < nch; ch++) {
        CP_WAIT1();                 // stage ch complete (ch+1 may be in flight)
        __syncthreads();
        const uint32_t buf = sbase + (uint32_t)((ch % 3) * STAGE_BYTES);

        if (ch + 2 < nch)
            issue_stage(sbase + (uint32_t)(((ch + 2) % 3) * STAGE_BYTES),
                        (ch + 2) * 64);
        CP_COMMIT();                // keep group count in lockstep

#pragma unroll
        for (int s = 0; s < 4; s++) {
            uint32_t ah[2][4], al[2][4];
#pragma unroll
            for (int mi = 0; mi < 2; mi++) {
                uint32_t ra = buf + (uint32_t)((wm + mi * 16 + a_row) * PITCH_B)
                                  + (uint32_t)(s * 32) + a_koff;
                ldsm4(ah[mi], ra);
                ldsm4(al[mi], ra + AMAT);
            }
            uint32_t bq[2][4];
#pragma unroll
            for (int p = 0; p < 2; p++) {
                uint32_t rb = buf + 2u * AMAT
                                  + (uint32_t)((wn + p * 16 + b_row) * PITCH_B)
                                  + (uint32_t)(s * 32) + b_koff;
                ldsm4(bq[p], rb);
            }
            // all 8 ah-MMAs (independent pacc targets), then all 8 al-MMAs:
            // RAW distance 8 covers MMA writeback latency.
#pragma unroll
            for (int ni = 0; ni < 4; ni++) {
                uint32_t b0 = bq[ni >> 1][(ni & 1) * 2];
                uint32_t b1 = bq[ni >> 1][(ni & 1) * 2 + 1];
#pragma unroll
                for (int mi = 0; mi < 2; mi++)
                    mma16816(pacc[mi][ni], ah[mi], b0, b1);
            }
#pragma unroll
            for (int ni = 0; ni < 4; ni++) {
                uint32_t b0 = bq[ni >> 1][(ni & 1) * 2];
                uint32_t b1 = bq[ni >> 1][(ni & 1) * 2 + 1];
#pragma unroll
                for (int mi = 0; mi < 2; mi++)
                    mma16816(pacc[mi][ni], al[mi], b0, b1);
            }
            // group-boundary flush: acc += s[g][n] * pacc
            int ent = ssched[ch * 4 + s];
            if (ent & 0x100) {
#pragma unroll
                for (int ni = 0; ni < 4; ni++) {
                    float s0, s1;
                    if constexpr (G2) {
                        const float* sp = sc + ((size_t)e * G + (ent & 0xFF)) * NSC
                                             + n0 + wn + ni * 8 + lc;
                        float2 sv = __ldg((const float2*)sp);
                        s0 = sv.x; s1 = sv.y;
                    } else {
                        const float* srow = stile + (ent & 0xFF) * 128;
                        s0 = srow[wn + ni * 8 + lc];
                        s1 = srow[wn + ni * 8 + lc + 1];
                    }
#pragma unroll
                    for (int mi = 0; mi < 2; mi++) {
                        acc[mi][ni][0] += s0 * pacc[mi][ni][0];
                        acc[mi][ni][1] += s1 * pacc[mi][ni][1];
                        acc[mi][ni][2] += s0 * pacc[mi][ni][2];
                        acc[mi][ni][3] += s1 * pacc[mi][ni][3];
                        pacc[mi][ni][0] = 0.0f; pacc[mi][ni][1] = 0.0f;
                        pacc[mi][ni][2] = 0.0f; pacc[mi][ni][3] = 0.0f;
                    }
                }
            }
        }
    }

    // epilogue: acc (fully scaled) -> global fp32
    const int lr = lid >> 2;
#pragma unroll
    for (int mi = 0; mi < 2; mi++) {
#pragma unroll
        for (int half = 0; half < 2; half++) {
            int row = m0 + wm + mi * 16 + half * 8 + lr;
            if (row < cnt) {
                int gs = base + row;
                if constexpr (!G2) {
                    float* dst = g_h + (size_t)gs * (2 * ID) + n0 + wn + lc;
#pragma unroll
                    for (int ni = 0; ni < 4; ni++) {
                        float2 v = make_float2(acc[mi][ni][half * 2],
                                               acc[mi][ni][half * 2 + 1]);
                        *(float2*)(dst + ni * 8) = v;
                    }
                } else {
                    float w = g_slot_w[gs];
                    float* dst = g_outslot + (size_t)gs * HD + n0 + wn + lc;
#pragma unroll
                    for (int ni = 0; ni < 4; ni++) {
                        float2 v = make_float2(acc[mi][ni][half * 2] * w,
                                               acc[mi][ni][half * 2 + 1] * w);
                        *(float2*)(dst + ni * 8) = v;
                    }
                }
            }
        }
    }
}

#define SMEM1 (3 * STAGE_BYTES + 8 * 128 * 4 + SCHED13 * 4)   // 114,976
#define SMEM2 (3 * STAGE_BYTES + SCHED2 * 4)                  // 111,744

// ---------------- combine: out[t] = outslot[s0] + outslot[s1] --------------
__global__ void k_combine(float* __restrict__ out) {
    int t = blockIdx.y;
    int n = blockIdx.x * 256 + threadIdx.x;
    int s0 = g_token_slot[t * 2 + 0];
    int s1 = g_token_slot[t * 2 + 1];
    out[(size_t)t * HD + n] = g_outslot[(size_t)s0 * HD + n] +
                              g_outslot[(size_t)s1 * HD + n];
}

// ---------------- launch ----------------------------------------------------
extern "C" void kernel_launch(void* const* d_in, const int* in_sizes, int n_in,
                              void* d_out, int out_size) {
    const float* x      = (const float*)d_in[0];
    const float* logits = (const float*)d_in[1];
    const int*   w13_q  = (const int*)  d_in[2];
    const int*   w2_q   = (const int*)  d_in[3];
    const float* w13_s  = (const float*)d_in[4];
    const float* w2_s   = (const float*)d_in[5];
    const int*   w13_g  = (const int*)  d_in[6];
    const int*   w2_g   = (const int*)  d_in[7];
    float* out = (float*)d_out;
    (void)in_sizes; (void)n_in; (void)out_size;

    static int s_attr_done = 0;
    if (!s_attr_done) {
        cudaFuncSetAttribute(k_gemm<K13P, 8, 8192, false>,
                             cudaFuncAttributeMaxDynamicSharedMemorySize, SMEM1);
        cudaFuncSetAttribute(k_gemm<K2P, 32, 1024, true>,
                             cudaFuncAttributeMaxDynamicSharedMemorySize, SMEM2);
        s_attr_done = 1;
    }

    // launch order: gemm1 is our launch index 3 -> the one ncu captures
    k_route<<<17, 256>>>(logits, w13_g, w2_g);                 // 0
    k_split_w13<<<dim3(128, NEXP), 256>>>(w13_q);              // 1
    k_split_x<<<(NSLOT * (K13P / 8)) / 256, 256>>>(x);         // 2

    // GEMM1: h = x @ q13^T with group-scale flush (y = 64 n-tiles)
    k_gemm<K13P, 8, 8192, false>
        <<<dim3(NTILES, 2 * ID / 128), GTHREADS, SMEM1>>>(w13_s); // 3

    k_split_w2<<<dim3(128, NEXP), 256>>>(w2_q);                // 4
    k_act<<<NSLOT, 256>>>();                                   // 5

    // GEMM2: outslot = act @ q2^T (y = 8 n-tiles)
    k_gemm<K2P, 32, 1024, true>
        <<<dim3(NTILES, HD / 128), GTHREADS, SMEM2>>>(w2_s);   // 6

    k_combine<<<dim3(HD / 256, T_TOK), 256>>>(out);            // 7
}

// round 17
// speedup vs baseline: 1.2299x; 1.0534x over previous
#include <cuda_runtime.h>
#include <cuda_bf16.h>
#include <cstdint>

// Problem constants (fixed by setup_inputs)
#define T_TOK 2048
#define NEXP  8
#define HD    1024
#define ID    4096
#define NSLOT 4096
#define PADROWS (NSLOT + 256)
#define NTILES  40              // max m-tiles of 128 over experts: 32 + 8

// permuted-k geometry: groups padded to 16, totals padded to 64
#define K13P   1152             // >= 1024 + 8*15, mult of 64
#define K2P    4608             // >= 4096 + 32*15, mult of 64
#define SCHED13 72              // 16-step entries
#define SCHED2  288

// ---------------- scratch (static device globals; no allocation) -----------
__device__ int   g_counts[NEXP];
__device__ int   g_base[NEXP];
__device__ int   g_slot_tok[NSLOT];
__device__ int   g_slot_e[NSLOT];
__device__ float g_slot_w[NSLOT];
__device__ int   g_token_slot[NSLOT];
__device__ int   g_tile_e[NTILES];
__device__ int   g_tile_m0[NTILES];

__device__ int   g_perm13[NEXP * K13P];
__device__ int   g_perm2 [NEXP * K2P];
__device__ int   g_sched13[NEXP * SCHED13];   // gid | 0x100 flush flag
__device__ int   g_sched2 [NEXP * SCHED2];
__device__ int   g_nch13[NEXP];
__device__ int   g_nch2 [NEXP];
__device__ int   g_gnext13[NEXP * 8];         // next present group or -1
__device__ int   g_gnext2 [NEXP * 32];

// telescoping flush ratios: ratio[e][g][n] = s'_g[n]/s'_gnext[n] (last: s'_g[n])
__device__ __align__(256) float g_ratio13[(size_t)NEXP * 8 * 8192];
__device__ __align__(256) float g_ratio2 [(size_t)NEXP * 32 * 1024];

// exact-integer weights (bf16 of q-8), k-permuted, [e][n][k']
__device__ __align__(256) __nv_bfloat16 g_q13p[(size_t)NEXP * 2 * ID * K13P];
__device__ __align__(256) __nv_bfloat16 g_q2p [(size_t)NEXP * HD * K2P];
// hi/lo split activations, k-permuted per slot's expert
__device__ __align__(256) __nv_bfloat16 g_xah [(size_t)PADROWS * K13P];
__device__ __align__(256) __nv_bfloat16 g_xal [(size_t)PADROWS * K13P];
__device__ __align__(256) __nv_bfloat16 g_acth[(size_t)PADROWS * K2P];
__device__ __align__(256) __nv_bfloat16 g_actl[(size_t)PADROWS * K2P];

__device__ __align__(256) float g_h[(size_t)NSLOT * 2 * ID];    // gemm1 out fp32
__device__ __align__(256) float g_outslot[(size_t)NSLOT * HD];  // gemm2 out fp32

// ---------------- helpers ---------------------------------------------------
__device__ __forceinline__ uint32_t smem_u32(const void* p) {
    uint32_t a;
    asm("{ .reg .u64 t; cvta.to.shared.u64 t, %1; cvt.u32.u64 %0, t; }"
        : "=r"(a) : "l"(p));
    return a;
}
__device__ __forceinline__ void ldsm4(uint32_t* r, uint32_t a) {
    asm volatile("ldmatrix.sync.aligned.m8n8.x4.shared.b16 {%0,%1,%2,%3}, [%4];"
                 : "=r"(r[0]), "=r"(r[1]), "=r"(r[2]), "=r"(r[3]) : "r"(a));
}
__device__ __forceinline__ void cpasync16(uint32_t saddr, const void* gaddr) {
    asm volatile("cp.async.cg.shared.global [%0], [%1], 16;"
                 :: "r"(saddr), "l"(gaddr) : "memory");
}
#define CP_COMMIT() asm volatile("cp.async.commit_group;" ::: "memory")
#define CP_WAIT0()  asm volatile("cp.async.wait_group 0;" ::: "memory")

__device__ __forceinline__ void mma16816(float* d, const uint32_t* a,
                                         uint32_t b0, uint32_t b1) {
    asm("mma.sync.aligned.m16n8k16.row.col.f32.bf16.bf16.f32 "
        "{%0,%1,%2,%3}, {%4,%5,%6,%7}, {%8,%9}, {%0,%1,%2,%3};"
        : "+f"(d[0]), "+f"(d[1]), "+f"(d[2]), "+f"(d[3])
        : "r"(a[0]), "r"(a[1]), "r"(a[2]), "r"(a[3]), "r"(b0), "r"(b1));
}
__device__ __forceinline__ void split2(float v, __nv_bfloat16& h, __nv_bfloat16& l) {
    h = __float2bfloat16(v);
    l = __float2bfloat16(v - __bfloat162float(h));
}

// ---------------- routing + permutation build (grid = 17 blocks) -----------
__global__ void k_route(const float* __restrict__ logits,
                        const int* __restrict__ gi13,
                        const int* __restrict__ gi2) {
    const int tid = threadIdx.x;
    if (blockIdx.x == 0) {
        __shared__ int   csh[NEXP];
        __shared__ int   cur[NEXP];
        __shared__ int   te[NSLOT];
        __shared__ float tw[NSLOT];
        if (tid < NEXP) csh[tid] = 0;
        __syncthreads();
        for (int t = tid; t < T_TOK; t += 256) {
            float l[NEXP];
#pragma unroll
            for (int e = 0; e < NEXP; e++) l[e] = logits[t * NEXP + e];
            int i1 = 0; float m1 = l[0];
            int i2 = -1; float m2 = -3.0e38f;
#pragma unroll
            for (int e = 1; e < NEXP; e++) {
                if (l[e] > m1) { m2 = m1; i2 = i1; m1 = l[e]; i1 = e; }
                else if (l[e] > m2) { m2 = l[e]; i2 = e; }
            }
            float r  = expf(m2 - m1);
            float w1 = 1.0f / (1.0f + r);
            float w2 = r * w1;
            te[t * 2 + 0] = i1;  te[t * 2 + 1] = i2;
            tw[t * 2 + 0] = w1;  tw[t * 2 + 1] = w2;
            atomicAdd(&csh[i1], 1);
            atomicAdd(&csh[i2], 1);
        }
        __syncthreads();
        if (tid == 0) {
            int acc = 0;
            for (int e = 0; e < NEXP; e++) {
                g_counts[e] = csh[e];
                g_base[e]   = acc;
                cur[e]      = acc;
                acc += csh[e];
            }
            int nt = 0;
            for (int e = 0; e < NEXP; e++)
                for (int m0 = 0; m0 < csh[e]; m0 += 128) {
                    g_tile_e[nt]  = e;
                    g_tile_m0[nt] = m0;
                    nt++;
                }
            for (; nt < NTILES; nt++) g_tile_e[nt] = -1;
        }
        __syncthreads();
        for (int t = tid; t < T_TOK; t += 256) {
#pragma unroll
            for (int j = 0; j < 2; j++) {
                int e   = te[t * 2 + j];
                int pos = atomicAdd(&cur[e], 1);
                g_slot_tok[pos]         = t;
                g_slot_e[pos]           = e;
                g_slot_w[pos]           = tw[t * 2 + j];
                g_token_slot[t * 2 + j] = pos;
            }
        }
    } else {
        // permutation builder
        const int pb  = blockIdx.x - 1;     // 0..15
        const int mat = pb >> 3;            // 0: w13, 1: w2
        const int e   = pb & 7;
        const int K   = mat ? ID : HD;
        const int G   = mat ? 32 : 8;
        const int KP  = mat ? K2P : K13P;
        const int SC  = mat ? SCHED2 : SCHED13;
        const int* gi = mat ? (gi2 + e * ID) : (gi13 + e * HD);
        int* perm  = mat ? (g_perm2 + e * K2P)   : (g_perm13 + e * K13P);
        int* sched = mat ? (g_sched2 + e * SCHED2) : (g_sched13 + e * SCHED13);
        int* gnext = mat ? (g_gnext2 + e * 32)   : (g_gnext13 + e * 8);

        __shared__ int lh[256 * 32];        // per-thread local hist
        __shared__ int gstart[33];
        const int perth = K / 256;          // 4 or 16
        const int kb = tid * perth;
        for (int g = 0; g < G; g++) lh[tid * G + g] = 0;
        __syncthreads();
        for (int i = 0; i < perth; i++) lh[tid * G + gi[kb + i]]++;
        __syncthreads();
        if (tid == 0) {
            int acc = 0, step = 0;
            int gcnt[32];
            for (int g = 0; g < G; g++) {
                int c = 0;
                for (int t = 0; t < 256; t++) c += lh[t * G + g];
                gcnt[g] = c;
                gstart[g] = acc;
                int stp = (c + 15) >> 4;
                for (int s = 0; s < stp; s++)
                    sched[step++] = g | ((s == stp - 1) ? 0x100 : 0);
                acc += stp << 4;
            }
            int nch = (step + 3) >> 2;
            if (mat) g_nch2[e] = nch; else g_nch13[e] = nch;
            for (; step < nch * 4; step++) sched[step] = 0;
            for (; step < SC; step++) sched[step] = 0;
            // next-present-group chain (for telescoping ratios)
            int nxt = -1;
            for (int g = G - 1; g >= 0; g--) {
                gnext[g] = nxt;
                if (gcnt[g] > 0) nxt = g;
            }
        }
        __syncthreads();
        if (tid < G) {
            int off = gstart[tid];
            for (int t = 0; t < 256; t++) {
                int c = lh[t * G + tid];
                lh[t * G + tid] = off;
                off += c;
            }
        }
        __syncthreads();
        for (int i = tid; i < KP; i += 256) perm[i] = -1;
        __syncthreads();
        for (int i = 0; i < perth; i++) {
            int k = kb + i;
            int g = gi[k];
            perm[lh[tid * G + g]++] = k;
        }
    }
}

// ---------------- prolog: weights + ratio tables ----------------------------
// grid (140, NEXP): x<128 -> w13 dequant; 128..135 -> ratio13; 136..139 -> ratio2
__global__ void k_split_w13(const int* __restrict__ qw,
                            const float* __restrict__ sc13,
                            const float* __restrict__ sc2) {
    const int e  = blockIdx.y;
    const int tid = threadIdx.x;
    if (blockIdx.x < 128) {
        __shared__ int sq[128 * 65];            // [kp][nn], padded stride
        __shared__ int sperm[K13P];
        const int n0 = blockIdx.x * 64;
        for (int i = tid; i < 128 * 64; i += 256) {
            int kp = i >> 6, nn = i & 63;
            sq[kp * 65 + nn] = qw[((size_t)e * 128 + kp) * 8192 + n0 + nn];
        }
        for (int i = tid; i < K13P; i += 256) sperm[i] = g_perm13[e * K13P + i];
        __syncthreads();
        for (int c = tid; c < 64 * (K13P / 8); c += 256) {
            int oct = c % (K13P / 8);
            int nn  = c / (K13P / 8);
            alignas(16) __nv_bfloat16 out[8];
            int4 p0 = *(const int4*)&sperm[oct * 8];
            int4 p1 = *(const int4*)&sperm[oct * 8 + 4];
            int pk[8] = {p0.x, p0.y, p0.z, p0.w, p1.x, p1.y, p1.z, p1.w};
#pragma unroll
            for (int j = 0; j < 8; j++) {
                int k = pk[j];
                int v = (k < 0) ? 0 : (((sq[(k >> 3) * 65 + nn] >> ((k & 7) * 4)) & 15) - 8);
                out[j] = __float2bfloat16((float)v);
            }
            *(uint4*)(g_q13p + ((size_t)e * 8192 + n0 + nn) * K13P + oct * 8) = *(uint4*)out;
        }
    } else if (blockIdx.x < 136) {
        // ratio13: one block per group g
        int g  = blockIdx.x - 128;
        int gn = g_gnext13[e * 8 + g];
        for (int n = tid; n < 8192; n += 256) {
            float snum = fmaxf(sc13[((size_t)e * 8 + g) * 8192 + n], 1e-12f);
            float sden = (gn >= 0)
                ? fmaxf(sc13[((size_t)e * 8 + gn) * 8192 + n], 1e-12f) : 1.0f;
            g_ratio13[((size_t)e * 8 + g) * 8192 + n] = snum / sden;
        }
    } else {
        // ratio2: 4 blocks x 8 groups each
        int b2 = blockIdx.x - 136;
        for (int i = tid; i < 8 * 1024; i += 256) {
            int g = b2 * 8 + (i >> 10);
            int n = i & 1023;
            int gn = g_gnext2[e * 32 + g];
            float snum = fmaxf(sc2[((size_t)e * 32 + g) * 1024 + n], 1e-12f);
            float sden = (gn >= 0)
                ? fmaxf(sc2[((size_t)e * 32 + gn) * 1024 + n], 1e-12f) : 1.0f;
            g_ratio2[((size_t)e * 32 + g) * 1024 + n] = snum / sden;
        }
    }
}

__global__ void k_split_w2(const int* __restrict__ qw) {
    __shared__ int sq[512 * 9];             // [kp][nn], padded
    __shared__ int sperm[K2P];
    const int e  = blockIdx.y;
    const int n0 = blockIdx.x * 8;
    const int tid = threadIdx.x;
    for (int i = tid; i < 512 * 8; i += 256) {
        int kp = i >> 3, nn = i & 7;
        sq[kp * 9 + nn] = qw[((size_t)e * 512 + kp) * 1024 + n0 + nn];
    }
    for (int i = tid; i < K2P; i += 256) sperm[i] = g_perm2[e * K2P + i];
    __syncthreads();
    for (int c = tid; c < 8 * (K2P / 8); c += 256) {
        int oct = c % (K2P / 8);
        int nn  = c / (K2P / 8);
        alignas(16) __nv_bfloat16 out[8];
        int4 p0 = *(const int4*)&sperm[oct * 8];
        int4 p1 = *(const int4*)&sperm[oct * 8 + 4];
        int pk[8] = {p0.x, p0.y, p0.z, p0.w, p1.x, p1.y, p1.z, p1.w};
#pragma unroll
        for (int j = 0; j < 8; j++) {
            int k = pk[j];
            int v = (k < 0) ? 0 : (((sq[(k >> 3) * 9 + nn] >> ((k & 7) * 4)) & 15) - 8);
            out[j] = __float2bfloat16((float)v);
        }
        *(uint4*)(g_q2p + ((size_t)e * 1024 + n0 + nn) * K2P + oct * 8) = *(uint4*)out;
    }
}

// ---------------- prolog: gather x (permuted k), split hi/lo ----------------
__global__ void k_split_x(const float* __restrict__ x) {
    int id  = blockIdx.x * 256 + threadIdx.x;
    int oct = id % (K13P / 8);
    int s   = id / (K13P / 8);
    int e   = g_slot_e[s];
    int tok = g_slot_tok[s];
    const int* pm = g_perm13 + e * K13P + oct * 8;
    alignas(16) __nv_bfloat16 h[8], l[8];
#pragma unroll
    for (int j = 0; j < 8; j++) {
        int k = pm[j];
        float v = (k < 0) ? 0.0f : x[(size_t)tok * HD + k];
        split2(v, h[j], l[j]);
    }
    size_t o = (size_t)s * K13P + oct * 8;
    *(uint4*)(g_xah + o) = *(uint4*)h;
    *(uint4*)(g_xal + o) = *(uint4*)l;
}

// ---------------- activation: silu(gate)*up, permuted k2, split hi/lo ------
__global__ void k_act() {
    __shared__ float sa[ID];
    const int s   = blockIdx.x;
    const int tid = threadIdx.x;
    const int e   = g_slot_e[s];
    const float* gp = g_h + (size_t)s * (2 * ID);
    for (int i = tid; i < ID; i += 256) {
        float g = gp[i];
        float u = gp[ID + i];
        sa[i] = g / (1.0f + expf(-g)) * u;
    }
    __syncthreads();
    for (int oct = tid; oct < K2P / 8; oct += 256) {
        const int* pm = g_perm2 + e * K2P + oct * 8;
        alignas(16) __nv_bfloat16 h[8], l[8];
#pragma unroll
        for (int j = 0; j < 8; j++) {
            int k = pm[j];
            float v = (k < 0) ? 0.0f : sa[k];
            split2(v, h[j], l[j]);
        }
        size_t o = (size_t)s * K2P + oct * 8;
        *(uint4*)(g_acth + o) = *(uint4*)h;
        *(uint4*)(g_actl + o) = *(uint4*)l;
    }
}

// ---------------- HMMA 2-term exact-int GEMM, telescoping-scale ------------
// Block 128x128, BK=64, 256 thr / 8 warps as 4(m) x 2(n) of 32x64 tiles.
// Single fp32 accumulator; at each k-group boundary acc *= ratio[g][n]
// (= s'_g/s'_gnext; last group: s'_g), so acc ends fully scaled.
// 32x64 warp tile cuts smem bytes/MAC from 0.094 to 0.0625.
// Ratio tables are device globals referenced DIRECTLY in device code
// (R16 bug: passing a __device__ symbol from host passes the host shadow).
#define PITCH_B 144
#define AMAT    (128 * PITCH_B)              // 18432
#define STAGE_BYTES (3 * AMAT)               // 55296: A-hi, A-lo, B
#define GTHREADS    256
#define SMEM_G  (2 * STAGE_BYTES + SCHED2 * 4)   // 111,744

template<int KP, int G, int NSC, bool G2>
__global__ __launch_bounds__(GTHREADS, 2) void k_gemm() {
    extern __shared__ __align__(128) char smem[];
    const int e = g_tile_e[blockIdx.x];
    if (e < 0) return;
    const int m0   = g_tile_m0[blockIdx.x];
    const int cnt  = g_counts[e];
    const int base = g_base[e];
    const int n0   = blockIdx.y * 128;
    const int tid  = threadIdx.x;
    const int lid  = tid & 31;
    const int wid  = tid >> 5;
    const int wm   = (wid >> 1) * 32;   // warp m offset: 0,32,64,96
    const int wn   = (wid & 1) * 64;    // warp n offset: 0 / 64

    const __nv_bfloat16* Axh;
    const __nv_bfloat16* Axl;
    const __nv_bfloat16* Bq;
    const int* schedg;
    const float* gr;
    int nch;
    if constexpr (G2) {
        Axh = g_acth + (size_t)(base + m0) * KP;
        Axl = g_actl + (size_t)(base + m0) * KP;
        Bq  = g_q2p + (size_t)e * HD * KP + (size_t)n0 * KP;
        schedg = g_sched2 + e * SCHED2;
        gr  = g_ratio2;
        nch = g_nch2[e];
    } else {
        Axh = g_xah + (size_t)(base + m0) * KP;
        Axl = g_xal + (size_t)(base + m0) * KP;
        Bq  = g_q13p + (size_t)e * 2 * ID * KP + (size_t)n0 * KP;
        schedg = g_sched13 + e * SCHED13;
        gr  = g_ratio13;
        nch = g_nch13[e];
    }

    const uint32_t sbase = smem_u32(smem);
    int* ssched = (int*)(smem + 2 * STAGE_BYTES);
    for (int i = tid; i < nch * 4; i += GTHREADS) ssched[i] = schedg[i];

    float acc[2][8][4];
#pragma unroll
    for (int i = 0; i < 2; i++)
#pragma unroll
        for (int j = 0; j < 8; j++)
#pragma unroll
            for (int k = 0; k < 4; k++) acc[i][j][k] = 0.0f;

    const uint32_t a_row  = (uint32_t)(lid & 15);
    const uint32_t a_koff = (uint32_t)((lid >> 4) * 16);
    const uint32_t b_row  = (uint32_t)(((lid >> 4) & 1) * 8 + (lid & 7));
    const uint32_t b_koff = (uint32_t)(((lid >> 3) & 1) * 16);
    const int lc = (lid & 3) * 2;

    // stage fill: 3072 16B chunks (A-hi 1024, A-lo 1024, B 1024), 12/thread
    auto issue_stage = [&](uint32_t sb, int k0) {
#pragma unroll
        for (int it = 0; it < 12; it++) {
            int j = it * GTHREADS + tid;
            const __nv_bfloat16* src;
            uint32_t dst;
            if (j < 2048) {
                int mat = j >> 10, jj = j & 1023;
                int r = jj >> 3, c = jj & 7;
                src = (mat ? Axl : Axh) + (size_t)r * KP + k0 + c * 8;
                dst = (uint32_t)(mat * AMAT + r * PITCH_B + c * 16);
            } else {
                int jb = j - 2048;
                int r = jb >> 3, c = jb & 7;
                src = Bq + (size_t)r * KP + k0 + c * 8;
                dst = (uint32_t)(2 * AMAT + r * PITCH_B + c * 16);
            }
            cpasync16(sb + dst, src);
        }
        CP_COMMIT();
    };

    issue_stage(sbase, 0);

    for (int ch = 0; ch < nch; ch++) {
        CP_WAIT0();
        __syncthreads();
        const uint32_t buf = sbase + (uint32_t)((ch & 1) * STAGE_BYTES);

        if (ch + 1 < nch)
            issue_stage(sbase + (uint32_t)(((ch + 1) & 1) * STAGE_BYTES),
                        (ch + 1) * 64);

#pragma unroll
        for (int s = 0; s < 4; s++) {
            uint32_t ah[2][4], al[2][4];
#pragma unroll
            for (int mi = 0; mi < 2; mi++) {
                uint32_t ra = buf + (uint32_t)((wm + mi * 16 + a_row) * PITCH_B)
                                  + (uint32_t)(s * 32) + a_koff;
                ldsm4(ah[mi], ra);
                ldsm4(al[mi], ra + AMAT);
            }
            uint32_t bq[4][4];
#pragma unroll
            for (int p = 0; p < 4; p++) {
                uint32_t rb = buf + 2u * AMAT
                                  + (uint32_t)((wn + p * 16 + b_row) * PITCH_B)
                                  + (uint32_t)(s * 32) + b_koff;
                ldsm4(bq[p], rb);
            }
#pragma unroll
            for (int ni = 0; ni < 8; ni++) {
                uint32_t b0 = bq[ni >> 1][(ni & 1) * 2];
                uint32_t b1 = bq[ni >> 1][(ni & 1) * 2 + 1];
#pragma unroll
                for (int mi = 0; mi < 2; mi++)
                    mma16816(acc[mi][ni], ah[mi], b0, b1);
            }
#pragma unroll
            for (int ni = 0; ni < 8; ni++) {
                uint32_t b0 = bq[ni >> 1][(ni & 1) * 2];
                uint32_t b1 = bq[ni >> 1][(ni & 1) * 2 + 1];
#pragma unroll
                for (int mi = 0; mi < 2; mi++)
                    mma16816(acc[mi][ni], al[mi], b0, b1);
            }
            // group-boundary: acc *= ratio[g][n] (telescoping scale)
            int ent = ssched[ch * 4 + s];
            if (ent & 0x100) {
                const float* grow = gr + ((size_t)e * G + (ent & 0xFF)) * NSC
                                       + n0 + wn;
#pragma unroll
                for (int ni = 0; ni < 8; ni++) {
                    float2 rv = __ldg((const float2*)(grow + ni * 8 + lc));
#pragma unroll
                    for (int mi = 0; mi < 2; mi++) {
                        acc[mi][ni][0] *= rv.x;
                        acc[mi][ni][1] *= rv.y;
                        acc[mi][ni][2] *= rv.x;
                        acc[mi][ni][3] *= rv.y;
                    }
                }
            }
        }
    }

    // epilogue: acc (fully scaled) -> global fp32
    const int lr = lid >> 2;
#pragma unroll
    for (int mi = 0; mi < 2; mi++) {
#pragma unroll
        for (int half = 0; half < 2; half++) {
            int row = m0 + wm + mi * 16 + half * 8 + lr;
            if (row < cnt) {
                int gs = base + row;
                if constexpr (!G2) {
                    float* dst = g_h + (size_t)gs * (2 * ID) + n0 + wn + lc;
#pragma unroll
                    for (int ni = 0; ni < 8; ni++) {
                        float2 v = make_float2(acc[mi][ni][half * 2],
                                               acc[mi][ni][half * 2 + 1]);
                        *(float2*)(dst + ni * 8) = v;
                    }
                } else {
                    float w = g_slot_w[gs];
                    float* dst = g_outslot + (size_t)gs * HD + n0 + wn + lc;
#pragma unroll
                    for (int ni = 0; ni < 8; ni++) {
                        float2 v = make_float2(acc[mi][ni][half * 2] * w,
                                               acc[mi][ni][half * 2 + 1] * w);
                        *(float2*)(dst + ni * 8) = v;
                    }
                }
            }
        }
    }
}

// ---------------- combine: out[t] = outslot[s0] + outslot[s1] --------------
__global__ void k_combine(float* __restrict__ out) {
    int t = blockIdx.y;
    int n = blockIdx.x * 256 + threadIdx.x;
    int s0 = g_token_slot[t * 2 + 0];
    int s1 = g_token_slot[t * 2 + 1];
    out[(size_t)t * HD + n] = g_outslot[(size_t)s0 * HD + n] +
                              g_outslot[(size_t)s1 * HD + n];
}

// ---------------- launch ----------------------------------------------------
extern "C" void kernel_launch(void* const* d_in, const int* in_sizes, int n_in,
                              void* d_out, int out_size) {
    const float* x      = (const float*)d_in[0];
    const float* logits = (const float*)d_in[1];
    const int*   w13_q  = (const int*)  d_in[2];
    const int*   w2_q   = (const int*)  d_in[3];
    const float* w13_s  = (const float*)d_in[4];
    const float* w2_s   = (const float*)d_in[5];
    const int*   w13_g  = (const int*)  d_in[6];
    const int*   w2_g   = (const int*)  d_in[7];
    float* out = (float*)d_out;
    (void)in_sizes; (void)n_in; (void)out_size;

    static int s_attr_done = 0;
    if (!s_attr_done) {
        cudaFuncSetAttribute(k_gemm<K13P, 8, 8192, false>,
                             cudaFuncAttributeMaxDynamicSharedMemorySize, SMEM_G);
        cudaFuncSetAttribute(k_gemm<K2P, 32, 1024, true>,
                             cudaFuncAttributeMaxDynamicSharedMemorySize, SMEM_G);
        s_attr_done = 1;
    }

    // launch order: gemm1 is our launch index 3 -> the one ncu captures
    k_route<<<17, 256>>>(logits, w13_g, w2_g);                 // 0
    k_split_w13<<<dim3(140, NEXP), 256>>>(w13_q, w13_s, w2_s); // 1 (+ratios)
    k_split_x<<<(NSLOT * (K13P / 8)) / 256, 256>>>(x);         // 2

    // GEMM1: h = x @ q13^T, telescoping scales (y = 64 n-tiles)
    k_gemm<K13P, 8, 8192, false>
        <<<dim3(NTILES, 2 * ID / 128), GTHREADS, SMEM_G>>>();  // 3

    k_split_w2<<<dim3(128, NEXP), 256>>>(w2_q);                // 4
    k_act<<<NSLOT, 256>>>();                                   // 5

    // GEMM2: outslot = act @ q2^T (y = 8 n-tiles)
    k_gemm<K2P, 32, 1024, true>
        <<<dim3(NTILES, HD / 128), GTHREADS, SMEM_G>>>();      // 6

    k_combine<<<dim3(HD / 256, T_TOK), 256>>>(out);            // 7
}